// round 8
// baseline (speedup 1.0000x reference)
#include <cuda_runtime.h>
#include <cuda_bf16.h>

typedef unsigned long long u64;
typedef unsigned int u32;

#define MAXN 250048

// Scratch (allocation-free rule: __device__ globals)
__device__ float g_X  [(size_t)MAXN * 64];
__device__ float g_F1 [(size_t)MAXN * 64];
__device__ float g_D0 [(size_t)MAXN * 32];
__device__ float g_D1 [(size_t)MAXN * 32];
__device__ float g_AT8[(size_t)MAXN * 16];   // interleaved A8 | T8 (8+8 ch)
__device__ int   g_iT1[(size_t)MAXN * 27];
__device__ int   g_iT2[(size_t)MAXN * 27];
__device__ int   g_iTd[(size_t)MAXN * 8];
// fragment-packed tf32 weights
__device__ float g_WF1[27 * 4096];   // conv1
__device__ float g_WFd[8 * 2048];    // down
__device__ float g_WF0[81 * 256];    // rw00 (3 blocks as K=81)
__device__ float g_WF4[27 * 256];    // enc4
__device__ float g_WFp[3 * 256];     // rw10 pointwise (3 blocks, K=1)

__device__ __forceinline__ u64 pack2(float x) {
    u64 r;
    asm("mov.b64 %0, {%1, %1};" : "=l"(r) : "r"(__float_as_uint(x)));
    return r;
}
__device__ __forceinline__ void fma2(u64& acc, u64 a, u64 b) {
    asm("fma.rn.f32x2 %0, %1, %2, %0;" : "+l"(acc) : "l"(a), "l"(b));
}
__device__ __forceinline__ float2 unpack2(u64 v) {
    float2 r;
    r.x = __uint_as_float((u32)(v & 0xffffffffull));
    r.y = __uint_as_float((u32)(v >> 32));
    return r;
}
__device__ __forceinline__ u32 smem_u32(const void* p) {
    return (u32)__cvta_generic_to_shared(p);
}
__device__ __forceinline__ void cpasync16(u32 dst, const void* src, u32 ssz) {
    asm volatile("cp.async.ca.shared.global [%0], [%1], 16, %2;\n"
                 :: "r"(dst), "l"(src), "r"(ssz));
}
__device__ __forceinline__ void cp_commit() {
    asm volatile("cp.async.commit_group;\n");
}
template<int N>
__device__ __forceinline__ void cp_wait() {
    asm volatile("cp.async.wait_group %0;\n" :: "n"(N));
}
__device__ __forceinline__ float rna_tf32(float x) {
    u32 y;
    asm("cvt.rna.tf32.f32 %0, %1;" : "=r"(y) : "f"(x));
    return __uint_as_float(y);
}
__device__ __forceinline__ void mma8(float4& d, const float* a, float2 b) {
    asm("mma.sync.aligned.m16n8k8.row.col.f32.tf32.tf32.f32 "
        "{%0,%1,%2,%3}, {%4,%5,%6,%7}, {%8,%9}, {%0,%1,%2,%3};"
        : "+f"(d.x), "+f"(d.y), "+f"(d.z), "+f"(d.w)
        : "r"(__float_as_uint(a[0])), "r"(__float_as_uint(a[1])),
          "r"(__float_as_uint(a[2])), "r"(__float_as_uint(a[3])),
          "r"(__float_as_uint(b.x)),  "r"(__float_as_uint(b.y)));
}

// ---------------------------------------------------------------------------
__global__ void transpose_idx(const int* __restrict__ in, int* __restrict__ outT,
                              int Npt, int K)
{
    int p = blockIdx.x * blockDim.x + threadIdx.x;
    if (p < Npt)
        for (int k = 0; k < K; k++)
            outT[(size_t)k * Npt + p] = in[(size_t)p * K + k];
}

// W[k][ci][co] fp32 -> tf32 B-fragment order
__global__ void prep_wfrag(const float* __restrict__ W, float* __restrict__ Wf,
                           int K, int CIN, int COUT)
{
    int Q = CIN / 8, NT = COUT / 8;
    int total = K * Q * NT * 64;
    int e = blockIdx.x * 256 + threadIdx.x;
    if (e >= total) return;
    int j = e & 1;
    int lane = (e >> 1) & 31;
    int r = e >> 6;
    int nt = r % NT; r /= NT;
    int q = r % Q;  int k = r / Q;
    int ci = q * 8 + (lane & 3) + 4 * j;
    int co = nt * 8 + (lane >> 2);
    Wf[e] = rna_tf32(W[((size_t)k * CIN + ci) * COUT + co]);
}

// ---------------------------------------------------------------------------
// tf32 mma.sync gather-GEMM sparse conv.  128 points/CTA (=128 threads),
// 4 warps; warp w -> rows [32w,32w+32) as 2 m16 tiles.
// cp.async double-buffered over K offsets; accumulate across offsets in regs.
// OS = output row stride (output written at out[p*OS + c]).
// FUSEPW: at k==CK (center offset), also accumulate pointwise Wp (COUT=8)
// producing tp = relu(in[p] @ Wp + Bp) -> Tout (row stride OS as well).
// ---------------------------------------------------------------------------
template<int K, int CIN, int COUT, int OS, bool RELU, bool CVTOUT,
         bool FUSEPW, int CK>
__global__ void __launch_bounds__(128)
tf32_conv(const float* __restrict__ X, const int* __restrict__ idxT,
          const float* __restrict__ Wf, const float* __restrict__ Bb,
          float* __restrict__ out,
          const float* __restrict__ Wp, const float* __restrict__ Bp,
          float* __restrict__ Tout, int Nout)
{
    constexpr int NTHR = 128;
    constexpr int Q    = CIN / 8;
    constexpr int NT   = COUT / 8;
    constexpr int ASTG = NTHR * CIN;
    constexpr int WSTG = Q * NT * 64;
    constexpr int C4U  = CIN / 4;

    extern __shared__ float sm[];
    float* A0 = sm;
    float* A1 = sm + ASTG;
    float* W0 = sm + 2 * ASTG;
    float* W1 = W0 + WSTG;

    const int tid = threadIdx.x, wid = tid >> 5, lane = tid & 31;
    const int r7 = lane >> 2;
    const int cl = lane & 3;
    const int p0 = blockIdx.x * NTHR;
    const int gp = p0 + tid;
    const bool pv = gp < Nout;

    const u32 ab0 = smem_u32(A0), ab1 = smem_u32(A1);
    const u32 wb0 = smem_u32(W0), wb1 = smem_u32(W1);

    // pointwise B fragments (small, L2-resident)
    float2 b10[FUSEPW ? Q : 1];
    if (FUSEPW) {
#pragma unroll
        for (int q = 0; q < Q; q++)
            b10[q] = *(const float2*)(Wp + (q * 32 + lane) * 2);
    }

    auto prefetch = [&](int k, int b) {
        int src = pv ? idxT[(size_t)k * Nout + gp] : -1;
        const float* srow = X + (size_t)(src >= 0 ? src : 0) * CIN;
        u32 ssz = (src >= 0) ? 16u : 0u;
        u32 base = (b ? ab1 : ab0) + (u32)tid * (CIN * 4);
#pragma unroll
        for (int c4 = 0; c4 < C4U; c4++)
            cpasync16(base + ((u32)(c4 ^ (tid & 7)) << 4), srow + 4 * c4, ssz);
        const float4* wg = (const float4*)(Wf + (size_t)k * WSTG);
        u32 wdst = b ? wb1 : wb0;
        for (int e = tid; e < WSTG / 4; e += NTHR)
            cpasync16(wdst + 16u * e, wg + e, 16);
    };

    prefetch(0, 0);
    cp_commit();

    float4 acc[2][NT];
#pragma unroll
    for (int m = 0; m < 2; m++)
#pragma unroll
        for (int nt = 0; nt < NT; nt++)
            acc[m][nt] = make_float4(0.f, 0.f, 0.f, 0.f);
    float4 acc2[2];
    acc2[0] = acc2[1] = make_float4(0.f, 0.f, 0.f, 0.f);

#pragma unroll 1
    for (int k = 0; k < K; k++) {
        __syncthreads();
        if (k + 1 < K) { prefetch(k + 1, (k + 1) & 1); cp_commit(); cp_wait<1>(); }
        else           { cp_wait<0>(); }
        __syncthreads();

        const float* A  = (k & 1) ? A1 : A0;
        const float* Wk = (k & 1) ? W1 : W0;

#pragma unroll
        for (int q = 0; q < Q; q++) {
            const int c4a = ((2 * q) ^ r7) << 2;
            const int c4b = ((2 * q + 1) ^ r7) << 2;
            float a[2][4];
#pragma unroll
            for (int m = 0; m < 2; m++) {
                const int rl = wid * 32 + m * 16 + r7;
                a[m][0] = A[rl * CIN + c4a + cl];
                a[m][1] = A[(rl + 8) * CIN + c4a + cl];
                a[m][2] = A[rl * CIN + c4b + cl];
                a[m][3] = A[(rl + 8) * CIN + c4b + cl];
            }
#pragma unroll
            for (int nt = 0; nt < NT; nt++) {
                float2 b = *(const float2*)(Wk + ((q * NT + nt) * 32 + lane) * 2);
                mma8(acc[0][nt], a[0], b);
                mma8(acc[1][nt], a[1], b);
            }
            if (FUSEPW && k == CK) {
                mma8(acc2[0], a[0], b10[q]);
                mma8(acc2[1], a[1], b10[q]);
            }
        }
    }

    // epilogue
#pragma unroll
    for (int m = 0; m < 2; m++) {
        const int rlo = p0 + wid * 32 + m * 16 + r7;
        const int rhi = rlo + 8;
#pragma unroll
        for (int nt = 0; nt < NT; nt++) {
            const int c0 = nt * 8 + 2 * cl;
            const float b0 = Bb[c0], b1 = Bb[c0 + 1];
            float2 v0 = make_float2(acc[m][nt].x + b0, acc[m][nt].y + b1);
            float2 v1 = make_float2(acc[m][nt].z + b0, acc[m][nt].w + b1);
            if (RELU) {
                v0.x = fmaxf(v0.x, 0.f); v0.y = fmaxf(v0.y, 0.f);
                v1.x = fmaxf(v1.x, 0.f); v1.y = fmaxf(v1.y, 0.f);
            }
            if (CVTOUT) {
                v0.x = rna_tf32(v0.x); v0.y = rna_tf32(v0.y);
                v1.x = rna_tf32(v1.x); v1.y = rna_tf32(v1.y);
            }
            if (rlo < Nout) *(float2*)(out + (size_t)rlo * OS + c0) = v0;
            if (rhi < Nout) *(float2*)(out + (size_t)rhi * OS + c0) = v1;
        }
        if (FUSEPW) {
            const int c0 = 2 * cl;
            const float b0 = Bp[c0], b1 = Bp[c0 + 1];
            float2 v0 = make_float2(fmaxf(acc2[m].x + b0, 0.f),
                                    fmaxf(acc2[m].y + b1, 0.f));
            float2 v1 = make_float2(fmaxf(acc2[m].z + b0, 0.f),
                                    fmaxf(acc2[m].w + b1, 0.f));
            if (rlo < Nout) *(float2*)(Tout + (size_t)rlo * OS + c0) = v0;
            if (rhi < Nout) *(float2*)(Tout + (size_t)rhi * OS + c0) = v1;
        }
    }
}

// ---------------------------------------------------------------------------
// Fused inception tail over one idx2 walk.  AT8 holds [a8 | t8] per point
// (stride 16, 64B row -> 4 contiguous LDG.128 per neighbor):
//   acc0 = conv27(a8, W01) + b01           (COUT=16)
//   t    = relu(conv27(t8, W11) + b11)     (COUT=8, registers)
//   out1 = t @ W12 + b12                   (pointwise, 8->16)
//   ob[p, 0:16]  = acc0 + Rin[p, 0:16]
//   ob[p, 16:32] = out1 + Rin[p, 16:32]
// ---------------------------------------------------------------------------
template<int K>
__global__ void __launch_bounds__(256)
spconv_tail(const float* __restrict__ AT8, const int* __restrict__ idxT,
            const float* __restrict__ W01, const float* __restrict__ b01,
            const float* __restrict__ W11, const float* __restrict__ b11,
            const float* __restrict__ W12, const float* __restrict__ b12,
            const float* __restrict__ Rin, float* __restrict__ ob, int Nout)
{
    __shared__ float Wsh0[K * 8 * 16];
    __shared__ float Wsh1[K * 8 * 8];
    __shared__ float Wsh2[8 * 16];
    for (int e = threadIdx.x; e < K * 8 * 16; e += 256) Wsh0[e] = W01[e];
    for (int e = threadIdx.x; e < K * 8 * 8; e += 256)  Wsh1[e] = W11[e];
    if (threadIdx.x < 128) Wsh2[threadIdx.x] = W12[threadIdx.x];
    __syncthreads();

    const int p = blockIdx.x * 256 + threadIdx.x;
    if (p >= Nout) return;

    u64 acc0[8], acc1[4];
#pragma unroll
    for (int c = 0; c < 8; c++) acc0[c] = 0ull;
#pragma unroll
    for (int c = 0; c < 4; c++) acc1[c] = 0ull;

    const float4 z4 = make_float4(0.f, 0.f, 0.f, 0.f);
    int s_nxt = (K > 1) ? idxT[(size_t)Nout + p] : -1;
    int s0 = idxT[p];
    float4 a0 = z4, a1 = z4, t0 = z4, t1 = z4;
    if (s0 >= 0) {
        const float4* r = (const float4*)(AT8 + (size_t)s0 * 16);
        a0 = r[0]; a1 = r[1]; t0 = r[2]; t1 = r[3];
    }

#pragma unroll 1
    for (int k = 0; k < K; k++) {
        float4 na0 = z4, na1 = z4, nt0 = z4, nt1 = z4;
        if (k + 1 < K) {
            if (s_nxt >= 0) {
                const float4* r = (const float4*)(AT8 + (size_t)s_nxt * 16);
                na0 = r[0]; na1 = r[1]; nt0 = r[2]; nt1 = r[3];
            }
            s_nxt = (k + 2 < K) ? idxT[(size_t)(k + 2) * Nout + p] : -1;
        }
        {
            const float* wk = Wsh0 + k * 8 * 16;
            const float ga[8] = { a0.x, a0.y, a0.z, a0.w, a1.x, a1.y, a1.z, a1.w };
#pragma unroll
            for (int ci = 0; ci < 8; ci++) {
                u64 g2 = pack2(ga[ci]);
                const u64* wr = (const u64*)(wk + ci * 16);
#pragma unroll
                for (int cc = 0; cc < 8; cc++) fma2(acc0[cc], g2, wr[cc]);
            }
        }
        {
            const float* wk = Wsh1 + k * 8 * 8;
            const float gt[8] = { t0.x, t0.y, t0.z, t0.w, t1.x, t1.y, t1.z, t1.w };
#pragma unroll
            for (int ci = 0; ci < 8; ci++) {
                u64 g2 = pack2(gt[ci]);
                const u64* wr = (const u64*)(wk + ci * 8);
#pragma unroll
                for (int cc = 0; cc < 4; cc++) fma2(acc1[cc], g2, wr[cc]);
            }
        }
        a0 = na0; a1 = na1; t0 = nt0; t1 = nt1;
    }

    // t = relu(acc1 + b11)
    float t[8];
#pragma unroll
    for (int q = 0; q < 4; q++) {
        float2 v = unpack2(acc1[q]);
        t[2 * q]     = fmaxf(v.x + b11[2 * q], 0.f);
        t[2 * q + 1] = fmaxf(v.y + b11[2 * q + 1], 0.f);
    }

    // out1 = t @ W12 + b12 (pointwise 8->16)
    u64 acc2[8];
#pragma unroll
    for (int c = 0; c < 8; c++) acc2[c] = 0ull;
#pragma unroll
    for (int ci = 0; ci < 8; ci++) {
        u64 g2 = pack2(t[ci]);
        const u64* wr = (const u64*)(Wsh2 + ci * 16);
#pragma unroll
        for (int cc = 0; cc < 8; cc++) fma2(acc2[cc], g2, wr[cc]);
    }

    float* op = ob + (size_t)p * 32;
#pragma unroll
    for (int q = 0; q < 4; q++) {
        float2 v0 = unpack2(acc0[2 * q]);
        float2 v1 = unpack2(acc0[2 * q + 1]);
        float4 o = make_float4(v0.x + b01[4 * q], v0.y + b01[4 * q + 1],
                               v1.x + b01[4 * q + 2], v1.y + b01[4 * q + 3]);
        float4 r = *(const float4*)(Rin + (size_t)p * 32 + 4 * q);
        o.x += r.x; o.y += r.y; o.z += r.z; o.w += r.w;
        *(float4*)(op + 4 * q) = o;
    }
#pragma unroll
    for (int q = 0; q < 4; q++) {
        float2 v0 = unpack2(acc2[2 * q]);
        float2 v1 = unpack2(acc2[2 * q + 1]);
        float4 o = make_float4(v0.x + b12[4 * q], v0.y + b12[4 * q + 1],
                               v1.x + b12[4 * q + 2], v1.y + b12[4 * q + 3]);
        float4 r = *(const float4*)(Rin + (size_t)p * 32 + 16 + 4 * q);
        o.x += r.x; o.y += r.y; o.z += r.z; o.w += r.w;
        *(float4*)(op + 16 + 4 * q) = o;
    }
}

template<bool CVT>
__global__ void add_kernel(const float* __restrict__ a, const float* __restrict__ b,
                           float* __restrict__ o, long long n4)
{
    long long i = blockIdx.x * (long long)blockDim.x + threadIdx.x;
    if (i < n4) {
        float4 x = ((const float4*)a)[i];
        float4 y = ((const float4*)b)[i];
        x.x += y.x; x.y += y.y; x.z += y.z; x.w += y.w;
        if (CVT) {
            x.x = rna_tf32(x.x); x.y = rna_tf32(x.y);
            x.z = rna_tf32(x.z); x.w = rna_tf32(x.w);
        }
        ((float4*)o)[i] = x;
    }
}

// ---------------------------------------------------------------------------
template<int K, int CIN, int COUT, int OS, bool RELU, bool CVTOUT,
         bool FUSEPW, int CK>
static void launch_tf32(const float* X, const int* idxT, const float* Wf,
                        const float* B, float* out,
                        const float* Wp, const float* Bp, float* Tout, int Nout)
{
    constexpr int SMEM = (2 * 128 * CIN + 2 * (CIN / 8) * (COUT / 8) * 64) * 4;
    auto kfn = tf32_conv<K, CIN, COUT, OS, RELU, CVTOUT, FUSEPW, CK>;
    cudaFuncSetAttribute(kfn, cudaFuncAttributeMaxDynamicSharedMemorySize, SMEM);
    int grid = (Nout + 127) / 128;
    kfn<<<grid, 128, SMEM>>>(X, idxT, Wf, B, out, Wp, Bp, Tout, Nout);
}

extern "C" void kernel_launch(void* const* d_in, const int* in_sizes, int n_in,
                              void* d_out, int out_size)
{
    const float* x_feat = (const float*)d_in[0];
    const float* f1_ref = (const float*)d_in[1];
    const float* w1   = (const float*)d_in[2];
    const float* b1   = (const float*)d_in[3];
    const float* wd   = (const float*)d_in[4];
    const float* bd   = (const float*)d_in[5];
    const float* rw00 = (const float*)d_in[6];
    const float* rb00 = (const float*)d_in[7];
    const float* rw01 = (const float*)d_in[8];
    const float* rb01 = (const float*)d_in[9];
    const float* rw10 = (const float*)d_in[10];
    const float* rb10 = (const float*)d_in[11];
    const float* rw11 = (const float*)d_in[12];
    const float* rb11 = (const float*)d_in[13];
    const float* rw12 = (const float*)d_in[14];
    const float* rb12 = (const float*)d_in[15];
    const float* w4   = (const float*)d_in[16];
    const float* b4   = (const float*)d_in[17];
    const int* idx1 = (const int*)d_in[18];
    const int* idxd = (const int*)d_in[19];
    const int* idx2 = (const int*)d_in[20];

    int N  = in_sizes[0] / 64;
    int N2 = in_sizes[19] / 8;

    float *X, *F1, *D0, *D1, *AT8;
    float *WF1, *WFd, *WF0, *WF4, *WFp;
    int *iT1, *iT2, *iTd;
    cudaGetSymbolAddress((void**)&X,   g_X);
    cudaGetSymbolAddress((void**)&F1,  g_F1);
    cudaGetSymbolAddress((void**)&D0,  g_D0);
    cudaGetSymbolAddress((void**)&D1,  g_D1);
    cudaGetSymbolAddress((void**)&AT8, g_AT8);
    cudaGetSymbolAddress((void**)&iT1, g_iT1);
    cudaGetSymbolAddress((void**)&iT2, g_iT2);
    cudaGetSymbolAddress((void**)&iTd, g_iTd);
    cudaGetSymbolAddress((void**)&WF1, g_WF1);
    cudaGetSymbolAddress((void**)&WFd, g_WFd);
    cudaGetSymbolAddress((void**)&WF0, g_WF0);
    cudaGetSymbolAddress((void**)&WF4, g_WF4);
    cudaGetSymbolAddress((void**)&WFp, g_WFp);

    // --- launches 0..4: exactly what conv1 needs, plus down's prep ---
    transpose_idx<<<(N  + 255) / 256, 256>>>(idx1, iT1, N,  27);      // 0
    prep_wfrag<<<(27 * 4096 + 255) / 256, 256>>>(w1, WF1, 27, 64, 64); // 1
    long long n4 = (long long)N * 16;
    add_kernel<true><<<(int)((n4 + 255) / 256), 256>>>(x_feat, f1_ref, X, n4); // 2
    transpose_idx<<<(N2 + 255) / 256, 256>>>(idxd, iTd, N2, 8);       // 3
    prep_wfrag<<<(8 * 2048 + 255) / 256, 256>>>(wd, WFd, 8, 64, 32);  // 4

    // launch 5: conv1 (ncu -s 5 -c 1 captures this)
    launch_tf32<27, 64, 64, 64, true, true, false, 0>(
        X, iT1, WF1, b1, F1, nullptr, nullptr, nullptr, N);

    // down: K=8, 64->32, relu
    launch_tf32<8, 64, 32, 32, true, false, false, 0>(
        F1, iTd, WFd, bd, D0, nullptr, nullptr, nullptr, N2);

    // remaining prep (coarse lattice)
    transpose_idx<<<(N2 + 255) / 256, 256>>>(idx2, iT2, N2, 27);
    prep_wfrag<<<(81 * 256 + 255) / 256, 256>>>(rw00, WF0, 81, 32, 8);
    prep_wfrag<<<(27 * 256 + 255) / 256, 256>>>(w4,   WF4, 27, 32, 8);
    prep_wfrag<<<(3 * 256 + 255) / 256, 256>>>(rw10,  WFp, 3,  32, 8);

    float* bufs[2] = { D0, D1 };
    for (int i = 0; i < 3; i++) {
        float* in = bufs[i & 1];
        float* ob = bufs[(i + 1) & 1];

        // K1: AT8[:, :8] = relu(conv27(in, rw00)); AT8[:, 8:] = relu(in @ rw10)
        launch_tf32<27, 32, 8, 16, true, false, true, 13>(
            in, iT2, WF0 + (size_t)i * 27 * 256, rb00 + i * 8, AT8,
            WFp + (size_t)i * 256, rb10 + i * 8, AT8 + 8, N2);

        // K2: full inception tail (rw01 conv + rw11 conv + rw12 pw + resid)
        spconv_tail<27><<<(N2 + 255) / 256, 256>>>(
            AT8, iT2,
            rw01 + (size_t)i * 27 * 8 * 16, rb01 + i * 16,
            rw11 + (size_t)i * 27 * 8 * 8,  rb11 + i * 8,
            rw12 + (size_t)i * 8 * 16,      rb12 + i * 16,
            in, ob, N2);
    }

    // enc4: K=27, 32->8, no relu, straight to output
    launch_tf32<27, 32, 8, 8, false, false, false, 0>(
        bufs[1], iT2, WF4, b4, (float*)d_out, nullptr, nullptr, nullptr, N2);
}

// round 9
// speedup vs baseline: 1.0735x; 1.0735x over previous
#include <cuda_runtime.h>
#include <cuda_bf16.h>

typedef unsigned long long u64;
typedef unsigned int u32;

#define MAXN 250048

// Scratch (allocation-free rule: __device__ globals)
__device__ float g_X  [(size_t)MAXN * 64];
__device__ float g_F1 [(size_t)MAXN * 64];
__device__ float g_D0 [(size_t)MAXN * 32];
__device__ float g_D1 [(size_t)MAXN * 32];
__device__ float g_AT8[(size_t)MAXN * 16];   // interleaved A8 | T8
__device__ int   g_iT1[(size_t)MAXN * 27];
__device__ int   g_iT2[(size_t)MAXN * 27];
__device__ int   g_iTd[(size_t)MAXN * 8];
__device__ int   g_src[(size_t)MAXN * 27];   // compacted pair lists (per-k segments)
__device__ int   g_dst[(size_t)MAXN * 27];
__device__ int   g_cnt[32];
// fragment-packed tf32 weights
__device__ float g_WF1[27 * 4096];   // conv1
__device__ float g_WFd[8 * 2048];    // down
__device__ float g_WF0[81 * 256];    // rw00 (3 blocks as K=81)
__device__ float g_WF4[27 * 256];    // enc4
__device__ float g_WFp[3 * 256];     // rw10 pointwise

__device__ __forceinline__ u64 pack2(float x) {
    u64 r;
    asm("mov.b64 %0, {%1, %1};" : "=l"(r) : "r"(__float_as_uint(x)));
    return r;
}
__device__ __forceinline__ void fma2(u64& acc, u64 a, u64 b) {
    asm("fma.rn.f32x2 %0, %1, %2, %0;" : "+l"(acc) : "l"(a), "l"(b));
}
__device__ __forceinline__ float2 unpack2(u64 v) {
    float2 r;
    r.x = __uint_as_float((u32)(v & 0xffffffffull));
    r.y = __uint_as_float((u32)(v >> 32));
    return r;
}
__device__ __forceinline__ u32 smem_u32(const void* p) {
    return (u32)__cvta_generic_to_shared(p);
}
__device__ __forceinline__ void cpasync16(u32 dst, const void* src, u32 ssz) {
    asm volatile("cp.async.ca.shared.global [%0], [%1], 16, %2;\n"
                 :: "r"(dst), "l"(src), "r"(ssz));
}
__device__ __forceinline__ void cp_commit() {
    asm volatile("cp.async.commit_group;\n");
}
template<int N>
__device__ __forceinline__ void cp_wait() {
    asm volatile("cp.async.wait_group %0;\n" :: "n"(N));
}
__device__ __forceinline__ float rna_tf32(float x) {
    u32 y;
    asm("cvt.rna.tf32.f32 %0, %1;" : "=r"(y) : "f"(x));
    return __uint_as_float(y);
}
__device__ __forceinline__ void mma8(float4& d, const float* a, float2 b) {
    asm("mma.sync.aligned.m16n8k8.row.col.f32.tf32.tf32.f32 "
        "{%0,%1,%2,%3}, {%4,%5,%6,%7}, {%8,%9}, {%0,%1,%2,%3};"
        : "+f"(d.x), "+f"(d.y), "+f"(d.z), "+f"(d.w)
        : "r"(__float_as_uint(a[0])), "r"(__float_as_uint(a[1])),
          "r"(__float_as_uint(a[2])), "r"(__float_as_uint(a[3])),
          "r"(__float_as_uint(b.x)),  "r"(__float_as_uint(b.y)));
}

// ---------------------------------------------------------------------------
__global__ void zero_cnt_kernel() {
    if (threadIdx.x < 32) g_cnt[threadIdx.x] = 0;
}

__global__ void transpose_idx(const int* __restrict__ in, int* __restrict__ outT,
                              int Npt, int K)
{
    int p = blockIdx.x * blockDim.x + threadIdx.x;
    if (p < Npt)
        for (int k = 0; k < K; k++)
            outT[(size_t)k * Npt + p] = in[(size_t)p * K + k];
}

// Warp-aggregated per-k pair compaction (skips skipK; center handled densely).
__global__ void build_pairs(const int* __restrict__ idxT, int Npt, int K, int skipK)
{
    int p = blockIdx.x * 256 + threadIdx.x;
    int lane = threadIdx.x & 31;
    for (int k = 0; k < K; k++) {
        if (k == skipK) continue;
        int s = (p < Npt) ? idxT[(size_t)k * Npt + p] : -1;
        bool valid = (s >= 0);
        u32 m = __ballot_sync(0xffffffffu, valid);
        if (!m) continue;
        int leader = __ffs(m) - 1;
        int base = 0;
        if (lane == leader) base = atomicAdd(&g_cnt[k], __popc(m));
        base = __shfl_sync(0xffffffffu, base, leader);
        if (valid) {
            int off = base + __popc(m & ((1u << lane) - 1));
            g_src[(size_t)k * Npt + off] = s;
            g_dst[(size_t)k * Npt + off] = p;
        }
    }
}

// W[k][ci][co] fp32 -> tf32 B-fragment order
__global__ void prep_wfrag(const float* __restrict__ W, float* __restrict__ Wf,
                           int K, int CIN, int COUT)
{
    int Q = CIN / 8, NT = COUT / 8;
    int total = K * Q * NT * 64;
    int e = blockIdx.x * 256 + threadIdx.x;
    if (e >= total) return;
    int j = e & 1;
    int lane = (e >> 1) & 31;
    int r = e >> 6;
    int nt = r % NT; r /= NT;
    int q = r % Q;  int k = r / Q;
    int ci = q * 8 + (lane & 3) + 4 * j;
    int co = nt * 8 + (lane >> 2);
    Wf[e] = rna_tf32(W[((size_t)k * CIN + ci) * COUT + co]);
}

// ---------------------------------------------------------------------------
// Dense tf32 mma.sync gather-GEMM sparse conv (128 pts/CTA, cp.async pipe).
// ---------------------------------------------------------------------------
template<int K, int CIN, int COUT, int OS, bool RELU, bool CVTOUT,
         bool FUSEPW, int CK>
__global__ void __launch_bounds__(128)
tf32_conv(const float* __restrict__ X, const int* __restrict__ idxT,
          const float* __restrict__ Wf, const float* __restrict__ Bb,
          float* __restrict__ out,
          const float* __restrict__ Wp, const float* __restrict__ Bp,
          float* __restrict__ Tout, int Nout)
{
    constexpr int NTHR = 128;
    constexpr int Q    = CIN / 8;
    constexpr int NT   = COUT / 8;
    constexpr int ASTG = NTHR * CIN;
    constexpr int WSTG = Q * NT * 64;
    constexpr int C4U  = CIN / 4;

    extern __shared__ float sm[];
    float* A0 = sm;
    float* A1 = sm + ASTG;
    float* W0 = sm + 2 * ASTG;
    float* W1 = W0 + WSTG;

    const int tid = threadIdx.x, wid = tid >> 5, lane = tid & 31;
    const int r7 = lane >> 2;
    const int cl = lane & 3;
    const int p0 = blockIdx.x * NTHR;
    const int gp = p0 + tid;
    const bool pv = gp < Nout;

    const u32 ab0 = smem_u32(A0), ab1 = smem_u32(A1);
    const u32 wb0 = smem_u32(W0), wb1 = smem_u32(W1);

    float2 b10[FUSEPW ? Q : 1];
    if (FUSEPW) {
#pragma unroll
        for (int q = 0; q < Q; q++)
            b10[q] = *(const float2*)(Wp + (q * 32 + lane) * 2);
    }

    auto prefetch = [&](int k, int b) {
        int src = pv ? idxT[(size_t)k * Nout + gp] : -1;
        const float* srow = X + (size_t)(src >= 0 ? src : 0) * CIN;
        u32 ssz = (src >= 0) ? 16u : 0u;
        u32 base = (b ? ab1 : ab0) + (u32)tid * (CIN * 4);
#pragma unroll
        for (int c4 = 0; c4 < C4U; c4++)
            cpasync16(base + ((u32)(c4 ^ (tid & 7)) << 4), srow + 4 * c4, ssz);
        const float4* wg = (const float4*)(Wf + (size_t)k * WSTG);
        u32 wdst = b ? wb1 : wb0;
        for (int e = tid; e < WSTG / 4; e += NTHR)
            cpasync16(wdst + 16u * e, wg + e, 16);
    };

    prefetch(0, 0);
    cp_commit();

    float4 acc[2][NT];
#pragma unroll
    for (int m = 0; m < 2; m++)
#pragma unroll
        for (int nt = 0; nt < NT; nt++)
            acc[m][nt] = make_float4(0.f, 0.f, 0.f, 0.f);
    float4 acc2[2];
    acc2[0] = acc2[1] = make_float4(0.f, 0.f, 0.f, 0.f);

#pragma unroll 1
    for (int k = 0; k < K; k++) {
        __syncthreads();
        if (k + 1 < K) { prefetch(k + 1, (k + 1) & 1); cp_commit(); cp_wait<1>(); }
        else           { cp_wait<0>(); }
        __syncthreads();

        const float* A  = (k & 1) ? A1 : A0;
        const float* Wk = (k & 1) ? W1 : W0;

#pragma unroll
        for (int q = 0; q < Q; q++) {
            const int c4a = ((2 * q) ^ r7) << 2;
            const int c4b = ((2 * q + 1) ^ r7) << 2;
            float a[2][4];
#pragma unroll
            for (int m = 0; m < 2; m++) {
                const int rl = wid * 32 + m * 16 + r7;
                a[m][0] = A[rl * CIN + c4a + cl];
                a[m][1] = A[(rl + 8) * CIN + c4a + cl];
                a[m][2] = A[rl * CIN + c4b + cl];
                a[m][3] = A[(rl + 8) * CIN + c4b + cl];
            }
#pragma unroll
            for (int nt = 0; nt < NT; nt++) {
                float2 b = *(const float2*)(Wk + ((q * NT + nt) * 32 + lane) * 2);
                mma8(acc[0][nt], a[0], b);
                mma8(acc[1][nt], a[1], b);
            }
            if (FUSEPW && k == CK) {
                mma8(acc2[0], a[0], b10[q]);
                mma8(acc2[1], a[1], b10[q]);
            }
        }
    }

#pragma unroll
    for (int m = 0; m < 2; m++) {
        const int rlo = p0 + wid * 32 + m * 16 + r7;
        const int rhi = rlo + 8;
#pragma unroll
        for (int nt = 0; nt < NT; nt++) {
            const int c0 = nt * 8 + 2 * cl;
            const float b0 = Bb[c0], b1 = Bb[c0 + 1];
            float2 v0 = make_float2(acc[m][nt].x + b0, acc[m][nt].y + b1);
            float2 v1 = make_float2(acc[m][nt].z + b0, acc[m][nt].w + b1);
            if (RELU) {
                v0.x = fmaxf(v0.x, 0.f); v0.y = fmaxf(v0.y, 0.f);
                v1.x = fmaxf(v1.x, 0.f); v1.y = fmaxf(v1.y, 0.f);
            }
            if (CVTOUT) {
                v0.x = rna_tf32(v0.x); v0.y = rna_tf32(v0.y);
                v1.x = rna_tf32(v1.x); v1.y = rna_tf32(v1.y);
            }
            if (rlo < Nout) *(float2*)(out + (size_t)rlo * OS + c0) = v0;
            if (rhi < Nout) *(float2*)(out + (size_t)rhi * OS + c0) = v1;
        }
        if (FUSEPW) {
            const int c0 = 2 * cl;
            const float b0 = Bp[c0], b1 = Bp[c0 + 1];
            float2 v0 = make_float2(fmaxf(acc2[m].x + b0, 0.f),
                                    fmaxf(acc2[m].y + b1, 0.f));
            float2 v1 = make_float2(fmaxf(acc2[m].z + b0, 0.f),
                                    fmaxf(acc2[m].w + b1, 0.f));
            if (rlo < Nout) *(float2*)(Tout + (size_t)rlo * OS + c0) = v0;
            if (rhi < Nout) *(float2*)(Tout + (size_t)rhi * OS + c0) = v1;
        }
    }
}

// ---------------------------------------------------------------------------
// Compacted per-k gather-GEMM-scatter: 128 compacted rows per CTA,
// segment k at g_src/g_dst[k*segStride ...], count g_cnt[k].
// out[dst] += row @ W[k]  via fp32 atomicAdd.
// ---------------------------------------------------------------------------
template<int CIN, int COUT>
__global__ void __launch_bounds__(128)
compact_gemm(const float* __restrict__ X, const float* __restrict__ Wf,
             int segStride, float* __restrict__ out)
{
    constexpr int Q    = CIN / 8;
    constexpr int NT   = COUT / 8;
    constexpr int WSTG = Q * NT * 64;
    constexpr int C4U  = CIN / 4;

    const int k = blockIdx.y;
    const int n = g_cnt[k];
    const int r0 = blockIdx.x * 128;
    if (r0 >= n) return;

    extern __shared__ float sm[];
    float* A  = sm;                  // 128*CIN
    float* Wk = sm + 128 * CIN;      // WSTG

    const int tid = threadIdx.x, wid = tid >> 5, lane = tid & 31;
    const int r7 = lane >> 2;
    const int cl = lane & 3;

    const u32 ab = smem_u32(A);
    const u32 wb = smem_u32(Wk);

    // gather one compacted row per thread + stage W[k]
    {
        int row = r0 + tid;
        int s = (row < n) ? g_src[(size_t)k * segStride + row] : -1;
        const float* srow = X + (size_t)(s >= 0 ? s : 0) * CIN;
        u32 ssz = (s >= 0) ? 16u : 0u;
        u32 base = ab + (u32)tid * (CIN * 4);
#pragma unroll
        for (int c4 = 0; c4 < C4U; c4++)
            cpasync16(base + ((u32)(c4 ^ (tid & 7)) << 4), srow + 4 * c4, ssz);
        const float4* wg = (const float4*)(Wf + (size_t)k * WSTG);
        for (int e = tid; e < WSTG / 4; e += 128)
            cpasync16(wb + 16u * e, wg + e, 16);
    }
    cp_commit();
    cp_wait<0>();
    __syncthreads();

    float4 acc[2][NT];
#pragma unroll
    for (int m = 0; m < 2; m++)
#pragma unroll
        for (int nt = 0; nt < NT; nt++)
            acc[m][nt] = make_float4(0.f, 0.f, 0.f, 0.f);

#pragma unroll
    for (int q = 0; q < Q; q++) {
        const int c4a = ((2 * q) ^ r7) << 2;
        const int c4b = ((2 * q + 1) ^ r7) << 2;
        float a[2][4];
#pragma unroll
        for (int m = 0; m < 2; m++) {
            const int rl = wid * 32 + m * 16 + r7;
            a[m][0] = A[rl * CIN + c4a + cl];
            a[m][1] = A[(rl + 8) * CIN + c4a + cl];
            a[m][2] = A[rl * CIN + c4b + cl];
            a[m][3] = A[(rl + 8) * CIN + c4b + cl];
        }
#pragma unroll
        for (int nt = 0; nt < NT; nt++) {
            float2 b = *(const float2*)(Wk + ((q * NT + nt) * 32 + lane) * 2);
            mma8(acc[0][nt], a[0], b);
            mma8(acc[1][nt], a[1], b);
        }
    }

    // scatter-add
#pragma unroll
    for (int m = 0; m < 2; m++) {
        const int rlo = r0 + wid * 32 + m * 16 + r7;
        const int rhi = rlo + 8;
        int dlo = (rlo < n) ? g_dst[(size_t)k * segStride + rlo] : -1;
        int dhi = (rhi < n) ? g_dst[(size_t)k * segStride + rhi] : -1;
#pragma unroll
        for (int nt = 0; nt < NT; nt++) {
            const int c0 = nt * 8 + 2 * cl;
            if (dlo >= 0) {
                atomicAdd(out + (size_t)dlo * COUT + c0,     acc[m][nt].x);
                atomicAdd(out + (size_t)dlo * COUT + c0 + 1, acc[m][nt].y);
            }
            if (dhi >= 0) {
                atomicAdd(out + (size_t)dhi * COUT + c0,     acc[m][nt].z);
                atomicAdd(out + (size_t)dhi * COUT + c0 + 1, acc[m][nt].w);
            }
        }
    }
}

// relu + tf32 round, in place
__global__ void relu_cvt_kernel(float* __restrict__ buf, long long n4)
{
    long long i = blockIdx.x * (long long)blockDim.x + threadIdx.x;
    if (i < n4) {
        float4 x = ((float4*)buf)[i];
        x.x = rna_tf32(fmaxf(x.x, 0.f)); x.y = rna_tf32(fmaxf(x.y, 0.f));
        x.z = rna_tf32(fmaxf(x.z, 0.f)); x.w = rna_tf32(fmaxf(x.w, 0.f));
        ((float4*)buf)[i] = x;
    }
}

// ---------------------------------------------------------------------------
// Fused inception tail (AT8 = [a8|t8] interleaved, stride 16), with
// validity skip: FMAs only when the neighbor exists.
// ---------------------------------------------------------------------------
template<int K>
__global__ void __launch_bounds__(256)
spconv_tail(const float* __restrict__ AT8, const int* __restrict__ idxT,
            const float* __restrict__ W01, const float* __restrict__ b01,
            const float* __restrict__ W11, const float* __restrict__ b11,
            const float* __restrict__ W12, const float* __restrict__ b12,
            const float* __restrict__ Rin, float* __restrict__ ob, int Nout)
{
    __shared__ float Wsh0[K * 8 * 16];
    __shared__ float Wsh1[K * 8 * 8];
    __shared__ float Wsh2[8 * 16];
    for (int e = threadIdx.x; e < K * 8 * 16; e += 256) Wsh0[e] = W01[e];
    for (int e = threadIdx.x; e < K * 8 * 8; e += 256)  Wsh1[e] = W11[e];
    if (threadIdx.x < 128) Wsh2[threadIdx.x] = W12[threadIdx.x];
    __syncthreads();

    const int p = blockIdx.x * 256 + threadIdx.x;
    if (p >= Nout) return;

    u64 acc0[8], acc1[4];
#pragma unroll
    for (int c = 0; c < 8; c++) acc0[c] = 0ull;
#pragma unroll
    for (int c = 0; c < 4; c++) acc1[c] = 0ull;

    const float4 z4 = make_float4(0.f, 0.f, 0.f, 0.f);
    int s_nxt = (K > 1) ? idxT[(size_t)Nout + p] : -1;
    int s0 = idxT[p];
    bool sv = (s0 >= 0);
    float4 a0 = z4, a1 = z4, t0 = z4, t1 = z4;
    if (sv) {
        const float4* r = (const float4*)(AT8 + (size_t)s0 * 16);
        a0 = r[0]; a1 = r[1]; t0 = r[2]; t1 = r[3];
    }

#pragma unroll 1
    for (int k = 0; k < K; k++) {
        float4 na0 = z4, na1 = z4, nt0 = z4, nt1 = z4;
        bool nv = false;
        if (k + 1 < K) {
            if (s_nxt >= 0) {
                nv = true;
                const float4* r = (const float4*)(AT8 + (size_t)s_nxt * 16);
                na0 = r[0]; na1 = r[1]; nt0 = r[2]; nt1 = r[3];
            }
            s_nxt = (k + 2 < K) ? idxT[(size_t)(k + 2) * Nout + p] : -1;
        }
        if (sv) {
            {
                const float* wk = Wsh0 + k * 8 * 16;
                const float ga[8] = { a0.x, a0.y, a0.z, a0.w, a1.x, a1.y, a1.z, a1.w };
#pragma unroll
                for (int ci = 0; ci < 8; ci++) {
                    u64 g2 = pack2(ga[ci]);
                    const u64* wr = (const u64*)(wk + ci * 16);
#pragma unroll
                    for (int cc = 0; cc < 8; cc++) fma2(acc0[cc], g2, wr[cc]);
                }
            }
            {
                const float* wk = Wsh1 + k * 8 * 8;
                const float gt[8] = { t0.x, t0.y, t0.z, t0.w, t1.x, t1.y, t1.z, t1.w };
#pragma unroll
                for (int ci = 0; ci < 8; ci++) {
                    u64 g2 = pack2(gt[ci]);
                    const u64* wr = (const u64*)(wk + ci * 8);
#pragma unroll
                    for (int cc = 0; cc < 4; cc++) fma2(acc1[cc], g2, wr[cc]);
                }
            }
        }
        a0 = na0; a1 = na1; t0 = nt0; t1 = nt1;
        sv = nv;
    }

    float t[8];
#pragma unroll
    for (int q = 0; q < 4; q++) {
        float2 v = unpack2(acc1[q]);
        t[2 * q]     = fmaxf(v.x + b11[2 * q], 0.f);
        t[2 * q + 1] = fmaxf(v.y + b11[2 * q + 1], 0.f);
    }

    u64 acc2[8];
#pragma unroll
    for (int c = 0; c < 8; c++) acc2[c] = 0ull;
#pragma unroll
    for (int ci = 0; ci < 8; ci++) {
        u64 g2 = pack2(t[ci]);
        const u64* wr = (const u64*)(Wsh2 + ci * 16);
#pragma unroll
        for (int cc = 0; cc < 8; cc++) fma2(acc2[cc], g2, wr[cc]);
    }

    float* op = ob + (size_t)p * 32;
#pragma unroll
    for (int q = 0; q < 4; q++) {
        float2 v0 = unpack2(acc0[2 * q]);
        float2 v1 = unpack2(acc0[2 * q + 1]);
        float4 o = make_float4(v0.x + b01[4 * q], v0.y + b01[4 * q + 1],
                               v1.x + b01[4 * q + 2], v1.y + b01[4 * q + 3]);
        float4 r = *(const float4*)(Rin + (size_t)p * 32 + 4 * q);
        o.x += r.x; o.y += r.y; o.z += r.z; o.w += r.w;
        *(float4*)(op + 4 * q) = o;
    }
#pragma unroll
    for (int q = 0; q < 4; q++) {
        float2 v0 = unpack2(acc2[2 * q]);
        float2 v1 = unpack2(acc2[2 * q + 1]);
        float4 o = make_float4(v0.x + b12[4 * q], v0.y + b12[4 * q + 1],
                               v1.x + b12[4 * q + 2], v1.y + b12[4 * q + 3]);
        float4 r = *(const float4*)(Rin + (size_t)p * 32 + 16 + 4 * q);
        o.x += r.x; o.y += r.y; o.z += r.z; o.w += r.w;
        *(float4*)(op + 16 + 4 * q) = o;
    }
}

template<bool CVT>
__global__ void add_kernel(const float* __restrict__ a, const float* __restrict__ b,
                           float* __restrict__ o, long long n4)
{
    long long i = blockIdx.x * (long long)blockDim.x + threadIdx.x;
    if (i < n4) {
        float4 x = ((const float4*)a)[i];
        float4 y = ((const float4*)b)[i];
        x.x += y.x; x.y += y.y; x.z += y.z; x.w += y.w;
        if (CVT) {
            x.x = rna_tf32(x.x); x.y = rna_tf32(x.y);
            x.z = rna_tf32(x.z); x.w = rna_tf32(x.w);
        }
        ((float4*)o)[i] = x;
    }
}

// ---------------------------------------------------------------------------
template<int K, int CIN, int COUT, int OS, bool RELU, bool CVTOUT,
         bool FUSEPW, int CK>
static void launch_tf32(const float* X, const int* idxT, const float* Wf,
                        const float* B, float* out,
                        const float* Wp, const float* Bp, float* Tout, int Nout)
{
    constexpr int SMEM = (2 * 128 * CIN + 2 * (CIN / 8) * (COUT / 8) * 64) * 4;
    auto kfn = tf32_conv<K, CIN, COUT, OS, RELU, CVTOUT, FUSEPW, CK>;
    cudaFuncSetAttribute(kfn, cudaFuncAttributeMaxDynamicSharedMemorySize, SMEM);
    int grid = (Nout + 127) / 128;
    kfn<<<grid, 128, SMEM>>>(X, idxT, Wf, B, out, Wp, Bp, Tout, Nout);
}

extern "C" void kernel_launch(void* const* d_in, const int* in_sizes, int n_in,
                              void* d_out, int out_size)
{
    const float* x_feat = (const float*)d_in[0];
    const float* f1_ref = (const float*)d_in[1];
    const float* w1   = (const float*)d_in[2];
    const float* b1   = (const float*)d_in[3];
    const float* wd   = (const float*)d_in[4];
    const float* bd   = (const float*)d_in[5];
    const float* rw00 = (const float*)d_in[6];
    const float* rb00 = (const float*)d_in[7];
    const float* rw01 = (const float*)d_in[8];
    const float* rb01 = (const float*)d_in[9];
    const float* rw10 = (const float*)d_in[10];
    const float* rb10 = (const float*)d_in[11];
    const float* rw11 = (const float*)d_in[12];
    const float* rb11 = (const float*)d_in[13];
    const float* rw12 = (const float*)d_in[14];
    const float* rb12 = (const float*)d_in[15];
    const float* w4   = (const float*)d_in[16];
    const float* b4   = (const float*)d_in[17];
    const int* idx1 = (const int*)d_in[18];
    const int* idxd = (const int*)d_in[19];
    const int* idx2 = (const int*)d_in[20];

    int N  = in_sizes[0] / 64;
    int N2 = in_sizes[19] / 8;

    float *X, *F1, *D0, *D1, *AT8;
    float *WF1, *WFd, *WF0, *WF4, *WFp;
    int *iT1, *iT2, *iTd;
    cudaGetSymbolAddress((void**)&X,   g_X);
    cudaGetSymbolAddress((void**)&F1,  g_F1);
    cudaGetSymbolAddress((void**)&D0,  g_D0);
    cudaGetSymbolAddress((void**)&D1,  g_D1);
    cudaGetSymbolAddress((void**)&AT8, g_AT8);
    cudaGetSymbolAddress((void**)&iT1, g_iT1);
    cudaGetSymbolAddress((void**)&iT2, g_iT2);
    cudaGetSymbolAddress((void**)&iTd, g_iTd);
    cudaGetSymbolAddress((void**)&WF1, g_WF1);
    cudaGetSymbolAddress((void**)&WFd, g_WFd);
    cudaGetSymbolAddress((void**)&WF0, g_WF0);
    cudaGetSymbolAddress((void**)&WF4, g_WF4);
    cudaGetSymbolAddress((void**)&WFp, g_WFp);

    // prep
    zero_cnt_kernel<<<1, 32>>>();
    transpose_idx<<<(N  + 255) / 256, 256>>>(idx1, iT1, N,  27);
    prep_wfrag<<<(27 * 4096 + 255) / 256, 256>>>(w1, WF1, 27, 64, 64);
    long long n4 = (long long)N * 16;
    add_kernel<true><<<(int)((n4 + 255) / 256), 256>>>(x_feat, f1_ref, X, n4);
    build_pairs<<<(N + 255) / 256, 256>>>(iT1, N, 27, 13);

    // conv1 center (k=13, always valid): F1 = X @ W13 + b1  (dense, no relu yet)
    launch_tf32<1, 64, 64, 64, false, false, false, 0>(
        X, iT1 + (size_t)13 * N, WF1 + (size_t)13 * 4096, b1, F1,
        nullptr, nullptr, nullptr, N);

    // conv1 non-center: compacted gather-GEMM-scatter into F1
    {
        constexpr int SMEM = (128 * 64 + 4096) * 4;
        auto kfn = compact_gemm<64, 64>;
        cudaFuncSetAttribute(kfn, cudaFuncAttributeMaxDynamicSharedMemorySize, SMEM);
        dim3 grid((N + 127) / 128, 27);
        kfn<<<grid, 128, SMEM>>>(X, WF1, N, F1);
    }

    // relu + tf32-round F1
    relu_cvt_kernel<<<(int)((n4 + 255) / 256), 256>>>(F1, n4);

    // down: dense K=8, 64->32, relu
    transpose_idx<<<(N2 + 255) / 256, 256>>>(idxd, iTd, N2, 8);
    prep_wfrag<<<(8 * 2048 + 255) / 256, 256>>>(wd, WFd, 8, 64, 32);
    launch_tf32<8, 64, 32, 32, true, false, false, 0>(
        F1, iTd, WFd, bd, D0, nullptr, nullptr, nullptr, N2);

    // coarse-lattice prep
    transpose_idx<<<(N2 + 255) / 256, 256>>>(idx2, iT2, N2, 27);
    prep_wfrag<<<(81 * 256 + 255) / 256, 256>>>(rw00, WF0, 81, 32, 8);
    prep_wfrag<<<(27 * 256 + 255) / 256, 256>>>(w4,   WF4, 27, 32, 8);
    prep_wfrag<<<(3 * 256 + 255) / 256, 256>>>(rw10,  WFp, 3,  32, 8);

    float* bufs[2] = { D0, D1 };
    for (int i = 0; i < 3; i++) {
        float* in = bufs[i & 1];
        float* ob = bufs[(i + 1) & 1];

        // K1: AT8[:, :8] = relu(conv27(in, rw00)); AT8[:, 8:] = relu(in @ rw10)
        launch_tf32<27, 32, 8, 16, true, false, true, 13>(
            in, iT2, WF0 + (size_t)i * 27 * 256, rb00 + i * 8, AT8,
            WFp + (size_t)i * 256, rb10 + i * 8, AT8 + 8, N2);

        // K2: full inception tail (rw01 conv + rw11 conv + rw12 pw + resid)
        spconv_tail<27><<<(N2 + 255) / 256, 256>>>(
            AT8, iT2,
            rw01 + (size_t)i * 27 * 8 * 16, rb01 + i * 16,
            rw11 + (size_t)i * 27 * 8 * 8,  rb11 + i * 8,
            rw12 + (size_t)i * 8 * 16,      rb12 + i * 16,
            in, ob, N2);
    }

    // enc4: K=27, 32->8, no relu, straight to output
    launch_tf32<27, 32, 8, 8, false, false, false, 0>(
        bufs[1], iT2, WF4, b4, (float*)d_out, nullptr, nullptr, nullptr, N2);
}

// round 10
// speedup vs baseline: 1.1024x; 1.0269x over previous
#include <cuda_runtime.h>
#include <cuda_bf16.h>

typedef unsigned long long u64;
typedef unsigned int u32;

#define MAXN 250048

// Scratch (allocation-free rule: __device__ globals)
__device__ float g_X  [(size_t)MAXN * 64];
__device__ float g_F1 [(size_t)MAXN * 64];
__device__ float g_D0 [(size_t)MAXN * 32];
__device__ float g_D1 [(size_t)MAXN * 32];
__device__ float g_AT8[(size_t)MAXN * 16];   // interleaved A8 | T8
__device__ int   g_iT1[(size_t)MAXN * 27];
__device__ int   g_iT2[(size_t)MAXN * 27];
__device__ int   g_iTd[(size_t)MAXN * 8];
__device__ int   g_src[(size_t)MAXN * 27];   // compacted pair lists (per-k segments)
__device__ int   g_dst[(size_t)MAXN * 27];
__device__ int   g_cnt[32];
// fragment-packed tf32 weights
__device__ float g_WF1[27 * 4096];   // conv1
__device__ float g_WFd[8 * 2048];    // down
__device__ float g_WF0[81 * 256];    // rw00 (3 blocks as K=81)
__device__ float g_WF4[27 * 256];    // enc4
__device__ float g_WFp[3 * 256];     // rw10 pointwise

__device__ __forceinline__ u64 pack2(float x) {
    u64 r;
    asm("mov.b64 %0, {%1, %1};" : "=l"(r) : "r"(__float_as_uint(x)));
    return r;
}
__device__ __forceinline__ void fma2(u64& acc, u64 a, u64 b) {
    asm("fma.rn.f32x2 %0, %1, %2, %0;" : "+l"(acc) : "l"(a), "l"(b));
}
__device__ __forceinline__ float2 unpack2(u64 v) {
    float2 r;
    r.x = __uint_as_float((u32)(v & 0xffffffffull));
    r.y = __uint_as_float((u32)(v >> 32));
    return r;
}
__device__ __forceinline__ u32 smem_u32(const void* p) {
    return (u32)__cvta_generic_to_shared(p);
}
__device__ __forceinline__ void cpasync16(u32 dst, const void* src, u32 ssz) {
    asm volatile("cp.async.ca.shared.global [%0], [%1], 16, %2;\n"
                 :: "r"(dst), "l"(src), "r"(ssz));
}
__device__ __forceinline__ void cp_commit() {
    asm volatile("cp.async.commit_group;\n");
}
template<int N>
__device__ __forceinline__ void cp_wait() {
    asm volatile("cp.async.wait_group %0;\n" :: "n"(N));
}
__device__ __forceinline__ float rna_tf32(float x) {
    u32 y;
    asm("cvt.rna.tf32.f32 %0, %1;" : "=r"(y) : "f"(x));
    return __uint_as_float(y);
}
__device__ __forceinline__ void mma8(float4& d, const float* a, float2 b) {
    asm("mma.sync.aligned.m16n8k8.row.col.f32.tf32.tf32.f32 "
        "{%0,%1,%2,%3}, {%4,%5,%6,%7}, {%8,%9}, {%0,%1,%2,%3};"
        : "+f"(d.x), "+f"(d.y), "+f"(d.z), "+f"(d.w)
        : "r"(__float_as_uint(a[0])), "r"(__float_as_uint(a[1])),
          "r"(__float_as_uint(a[2])), "r"(__float_as_uint(a[3])),
          "r"(__float_as_uint(b.x)),  "r"(__float_as_uint(b.y)));
}
__device__ __forceinline__ void red2(float* p, float x, float y) {
    asm volatile("red.global.add.v2.f32 [%0], {%1, %2};"
                 :: "l"(p), "f"(x), "f"(y) : "memory");
}

// ---------------------------------------------------------------------------
__global__ void zero_cnt_kernel() {
    if (threadIdx.x < 32) g_cnt[threadIdx.x] = 0;
}

__global__ void transpose_idx(const int* __restrict__ in, int* __restrict__ outT,
                              int Npt, int K)
{
    int p = blockIdx.x * blockDim.x + threadIdx.x;
    if (p < Npt)
        for (int k = 0; k < K; k++)
            outT[(size_t)k * Npt + p] = in[(size_t)p * K + k];
}

// Warp-aggregated per-k pair compaction (skips skipK; center handled densely).
__global__ void build_pairs(const int* __restrict__ idxT, int Npt, int K, int skipK)
{
    int p = blockIdx.x * 256 + threadIdx.x;
    int lane = threadIdx.x & 31;
    for (int k = 0; k < K; k++) {
        if (k == skipK) continue;
        int s = (p < Npt) ? idxT[(size_t)k * Npt + p] : -1;
        bool valid = (s >= 0);
        u32 m = __ballot_sync(0xffffffffu, valid);
        if (!m) continue;
        int leader = __ffs(m) - 1;
        int base = 0;
        if (lane == leader) base = atomicAdd(&g_cnt[k], __popc(m));
        base = __shfl_sync(0xffffffffu, base, leader);
        if (valid) {
            int off = base + __popc(m & ((1u << lane) - 1));
            g_src[(size_t)k * Npt + off] = s;
            g_dst[(size_t)k * Npt + off] = p;
        }
    }
}

// W[k][ci][co] fp32 -> tf32 B-fragment order
__global__ void prep_wfrag(const float* __restrict__ W, float* __restrict__ Wf,
                           int K, int CIN, int COUT)
{
    int Q = CIN / 8, NT = COUT / 8;
    int total = K * Q * NT * 64;
    int e = blockIdx.x * 256 + threadIdx.x;
    if (e >= total) return;
    int j = e & 1;
    int lane = (e >> 1) & 31;
    int r = e >> 6;
    int nt = r % NT; r /= NT;
    int q = r % Q;  int k = r / Q;
    int ci = q * 8 + (lane & 3) + 4 * j;
    int co = nt * 8 + (lane >> 2);
    Wf[e] = rna_tf32(W[((size_t)k * CIN + ci) * COUT + co]);
}

// ---------------------------------------------------------------------------
// Dense tf32 mma.sync gather-GEMM sparse conv (128 pts/CTA).
// PIPE-deep cp.async ring; per-stage idx register-prefetched one iter ahead.
// ---------------------------------------------------------------------------
template<int K, int CIN, int COUT, int OS, int PIPE, bool RELU, bool CVTOUT,
         bool FUSEPW, int CK>
__global__ void __launch_bounds__(128)
tf32_conv(const float* __restrict__ X, const int* __restrict__ idxT,
          const float* __restrict__ Wf, const float* __restrict__ Bb,
          float* __restrict__ out,
          const float* __restrict__ Wp, const float* __restrict__ Bp,
          float* __restrict__ Tout, int Nout)
{
    constexpr int NTHR = 128;
    constexpr int Q    = CIN / 8;
    constexpr int NT   = COUT / 8;
    constexpr int ASTG = NTHR * CIN;
    constexpr int WSTG = Q * NT * 64;
    constexpr int STG  = ASTG + WSTG;
    constexpr int C4U  = CIN / 4;

    extern __shared__ float sm[];

    const int tid = threadIdx.x, wid = tid >> 5, lane = tid & 31;
    const int r7 = lane >> 2;
    const int cl = lane & 3;
    const int p0 = blockIdx.x * NTHR;
    const int gp = p0 + tid;
    const bool pv = gp < Nout;

    float2 b10[FUSEPW ? Q : 1];
    if (FUSEPW) {
#pragma unroll
        for (int q = 0; q < Q; q++)
            b10[q] = *(const float2*)(Wp + (q * 32 + lane) * 2);
    }

    auto ldidx = [&](int k) -> int {
        return (pv && k < K) ? idxT[(size_t)k * Nout + gp] : -1;
    };

    auto prefetch = [&](int k, int src) {
        const int s = k % PIPE;
        const float* srow = X + (size_t)(src >= 0 ? src : 0) * CIN;
        u32 ssz = (src >= 0) ? 16u : 0u;
        u32 base = smem_u32(sm + s * STG) + (u32)tid * (CIN * 4);
#pragma unroll
        for (int c4 = 0; c4 < C4U; c4++)
            cpasync16(base + ((u32)(c4 ^ (tid & 7)) << 4), srow + 4 * c4, ssz);
        const float4* wg = (const float4*)(Wf + (size_t)k * WSTG);
        u32 wdst = smem_u32(sm + s * STG + ASTG);
        for (int e = tid; e < WSTG / 4; e += NTHR)
            cpasync16(wdst + 16u * e, wg + e, 16);
    };

    // prologue: stages 0..PIPE-2 (pad with empty commits if K < PIPE-1)
#pragma unroll
    for (int k = 0; k < PIPE - 1; k++) {
        if (k < K) prefetch(k, ldidx(k));
        cp_commit();
    }
    int src_nxt = ldidx(PIPE - 1);

    float4 acc[2][NT];
#pragma unroll
    for (int m = 0; m < 2; m++)
#pragma unroll
        for (int nt = 0; nt < NT; nt++)
            acc[m][nt] = make_float4(0.f, 0.f, 0.f, 0.f);
    float4 acc2[2];
    acc2[0] = acc2[1] = make_float4(0.f, 0.f, 0.f, 0.f);

#pragma unroll 1
    for (int k = 0; k < K; k++) {
        __syncthreads();                       // stage (k%PIPE) free for refill
        if (k + PIPE - 1 < K) prefetch(k + PIPE - 1, src_nxt);
        src_nxt = ldidx(k + PIPE);
        cp_commit();                           // possibly-empty group
        cp_wait<PIPE - 1>();                   // stage k drained
        __syncthreads();

        const float* A  = sm + (k % PIPE) * STG;
        const float* Wk = A + ASTG;

#pragma unroll
        for (int q = 0; q < Q; q++) {
            const int c4a = ((2 * q) ^ r7) << 2;
            const int c4b = ((2 * q + 1) ^ r7) << 2;
            float a[2][4];
#pragma unroll
            for (int m = 0; m < 2; m++) {
                const int rl = wid * 32 + m * 16 + r7;
                a[m][0] = A[rl * CIN + c4a + cl];
                a[m][1] = A[(rl + 8) * CIN + c4a + cl];
                a[m][2] = A[rl * CIN + c4b + cl];
                a[m][3] = A[(rl + 8) * CIN + c4b + cl];
            }
#pragma unroll
            for (int nt = 0; nt < NT; nt++) {
                float2 b = *(const float2*)(Wk + ((q * NT + nt) * 32 + lane) * 2);
                mma8(acc[0][nt], a[0], b);
                mma8(acc[1][nt], a[1], b);
            }
            if (FUSEPW && k == CK) {
                mma8(acc2[0], a[0], b10[q]);
                mma8(acc2[1], a[1], b10[q]);
            }
        }
    }

#pragma unroll
    for (int m = 0; m < 2; m++) {
        const int rlo = p0 + wid * 32 + m * 16 + r7;
        const int rhi = rlo + 8;
#pragma unroll
        for (int nt = 0; nt < NT; nt++) {
            const int c0 = nt * 8 + 2 * cl;
            const float b0 = Bb[c0], b1 = Bb[c0 + 1];
            float2 v0 = make_float2(acc[m][nt].x + b0, acc[m][nt].y + b1);
            float2 v1 = make_float2(acc[m][nt].z + b0, acc[m][nt].w + b1);
            if (RELU) {
                v0.x = fmaxf(v0.x, 0.f); v0.y = fmaxf(v0.y, 0.f);
                v1.x = fmaxf(v1.x, 0.f); v1.y = fmaxf(v1.y, 0.f);
            }
            if (CVTOUT) {
                v0.x = rna_tf32(v0.x); v0.y = rna_tf32(v0.y);
                v1.x = rna_tf32(v1.x); v1.y = rna_tf32(v1.y);
            }
            if (rlo < Nout) *(float2*)(out + (size_t)rlo * OS + c0) = v0;
            if (rhi < Nout) *(float2*)(out + (size_t)rhi * OS + c0) = v1;
        }
        if (FUSEPW) {
            const int c0 = 2 * cl;
            const float b0 = Bp[c0], b1 = Bp[c0 + 1];
            float2 v0 = make_float2(fmaxf(acc2[m].x + b0, 0.f),
                                    fmaxf(acc2[m].y + b1, 0.f));
            float2 v1 = make_float2(fmaxf(acc2[m].z + b0, 0.f),
                                    fmaxf(acc2[m].w + b1, 0.f));
            if (rlo < Nout) *(float2*)(Tout + (size_t)rlo * OS + c0) = v0;
            if (rhi < Nout) *(float2*)(Tout + (size_t)rhi * OS + c0) = v1;
        }
    }
}

// ---------------------------------------------------------------------------
// Compacted per-k gather-GEMM-scatter (conv1 non-center), v2 reductions.
// ---------------------------------------------------------------------------
template<int CIN, int COUT>
__global__ void __launch_bounds__(128)
compact_gemm(const float* __restrict__ X, const float* __restrict__ Wf,
             int segStride, float* __restrict__ out)
{
    constexpr int Q    = CIN / 8;
    constexpr int NT   = COUT / 8;
    constexpr int WSTG = Q * NT * 64;
    constexpr int C4U  = CIN / 4;

    const int k = blockIdx.y;
    const int n = g_cnt[k];
    const int r0 = blockIdx.x * 128;
    if (r0 >= n) return;

    extern __shared__ float sm[];
    float* A  = sm;
    float* Wk = sm + 128 * CIN;

    const int tid = threadIdx.x, wid = tid >> 5, lane = tid & 31;
    const int r7 = lane >> 2;
    const int cl = lane & 3;

    const u32 ab = smem_u32(A);
    const u32 wb = smem_u32(Wk);

    {
        int row = r0 + tid;
        int s = (row < n) ? g_src[(size_t)k * segStride + row] : -1;
        const float* srow = X + (size_t)(s >= 0 ? s : 0) * CIN;
        u32 ssz = (s >= 0) ? 16u : 0u;
        u32 base = ab + (u32)tid * (CIN * 4);
#pragma unroll
        for (int c4 = 0; c4 < C4U; c4++)
            cpasync16(base + ((u32)(c4 ^ (tid & 7)) << 4), srow + 4 * c4, ssz);
        const float4* wg = (const float4*)(Wf + (size_t)k * WSTG);
        for (int e = tid; e < WSTG / 4; e += 128)
            cpasync16(wb + 16u * e, wg + e, 16);
    }
    cp_commit();
    cp_wait<0>();
    __syncthreads();

    float4 acc[2][NT];
#pragma unroll
    for (int m = 0; m < 2; m++)
#pragma unroll
        for (int nt = 0; nt < NT; nt++)
            acc[m][nt] = make_float4(0.f, 0.f, 0.f, 0.f);

#pragma unroll
    for (int q = 0; q < Q; q++) {
        const int c4a = ((2 * q) ^ r7) << 2;
        const int c4b = ((2 * q + 1) ^ r7) << 2;
        float a[2][4];
#pragma unroll
        for (int m = 0; m < 2; m++) {
            const int rl = wid * 32 + m * 16 + r7;
            a[m][0] = A[rl * CIN + c4a + cl];
            a[m][1] = A[(rl + 8) * CIN + c4a + cl];
            a[m][2] = A[rl * CIN + c4b + cl];
            a[m][3] = A[(rl + 8) * CIN + c4b + cl];
        }
#pragma unroll
        for (int nt = 0; nt < NT; nt++) {
            float2 b = *(const float2*)(Wk + ((q * NT + nt) * 32 + lane) * 2);
            mma8(acc[0][nt], a[0], b);
            mma8(acc[1][nt], a[1], b);
        }
    }

    // scatter: vectorized reductions (channel pair is 8B-aligned)
#pragma unroll
    for (int m = 0; m < 2; m++) {
        const int rlo = r0 + wid * 32 + m * 16 + r7;
        const int rhi = rlo + 8;
        int dlo = (rlo < n) ? g_dst[(size_t)k * segStride + rlo] : -1;
        int dhi = (rhi < n) ? g_dst[(size_t)k * segStride + rhi] : -1;
#pragma unroll
        for (int nt = 0; nt < NT; nt++) {
            const int c0 = nt * 8 + 2 * cl;
            if (dlo >= 0)
                red2(out + (size_t)dlo * COUT + c0, acc[m][nt].x, acc[m][nt].y);
            if (dhi >= 0)
                red2(out + (size_t)dhi * COUT + c0, acc[m][nt].z, acc[m][nt].w);
        }
    }
}

// relu + tf32 round, in place
__global__ void relu_cvt_kernel(float* __restrict__ buf, long long n4)
{
    long long i = blockIdx.x * (long long)blockDim.x + threadIdx.x;
    if (i < n4) {
        float4 x = ((float4*)buf)[i];
        x.x = rna_tf32(fmaxf(x.x, 0.f)); x.y = rna_tf32(fmaxf(x.y, 0.f));
        x.z = rna_tf32(fmaxf(x.z, 0.f)); x.w = rna_tf32(fmaxf(x.w, 0.f));
        ((float4*)buf)[i] = x;
    }
}

// ---------------------------------------------------------------------------
// Fused inception tail (AT8 = [a8|t8] interleaved, stride 16) with validity skip
// ---------------------------------------------------------------------------
template<int K>
__global__ void __launch_bounds__(256)
spconv_tail(const float* __restrict__ AT8, const int* __restrict__ idxT,
            const float* __restrict__ W01, const float* __restrict__ b01,
            const float* __restrict__ W11, const float* __restrict__ b11,
            const float* __restrict__ W12, const float* __restrict__ b12,
            const float* __restrict__ Rin, float* __restrict__ ob, int Nout)
{
    __shared__ float Wsh0[K * 8 * 16];
    __shared__ float Wsh1[K * 8 * 8];
    __shared__ float Wsh2[8 * 16];
    for (int e = threadIdx.x; e < K * 8 * 16; e += 256) Wsh0[e] = W01[e];
    for (int e = threadIdx.x; e < K * 8 * 8; e += 256)  Wsh1[e] = W11[e];
    if (threadIdx.x < 128) Wsh2[threadIdx.x] = W12[threadIdx.x];
    __syncthreads();

    const int p = blockIdx.x * 256 + threadIdx.x;
    if (p >= Nout) return;

    u64 acc0[8], acc1[4];
#pragma unroll
    for (int c = 0; c < 8; c++) acc0[c] = 0ull;
#pragma unroll
    for (int c = 0; c < 4; c++) acc1[c] = 0ull;

    const float4 z4 = make_float4(0.f, 0.f, 0.f, 0.f);
    int s_nxt = (K > 1) ? idxT[(size_t)Nout + p] : -1;
    int s0 = idxT[p];
    bool sv = (s0 >= 0);
    float4 a0 = z4, a1 = z4, t0 = z4, t1 = z4;
    if (sv) {
        const float4* r = (const float4*)(AT8 + (size_t)s0 * 16);
        a0 = r[0]; a1 = r[1]; t0 = r[2]; t1 = r[3];
    }

#pragma unroll 1
    for (int k = 0; k < K; k++) {
        float4 na0 = z4, na1 = z4, nt0 = z4, nt1 = z4;
        bool nv = false;
        if (k + 1 < K) {
            if (s_nxt >= 0) {
                nv = true;
                const float4* r = (const float4*)(AT8 + (size_t)s_nxt * 16);
                na0 = r[0]; na1 = r[1]; nt0 = r[2]; nt1 = r[3];
            }
            s_nxt = (k + 2 < K) ? idxT[(size_t)(k + 2) * Nout + p] : -1;
        }
        if (sv) {
            {
                const float* wk = Wsh0 + k * 8 * 16;
                const float ga[8] = { a0.x, a0.y, a0.z, a0.w, a1.x, a1.y, a1.z, a1.w };
#pragma unroll
                for (int ci = 0; ci < 8; ci++) {
                    u64 g2 = pack2(ga[ci]);
                    const u64* wr = (const u64*)(wk + ci * 16);
#pragma unroll
                    for (int cc = 0; cc < 8; cc++) fma2(acc0[cc], g2, wr[cc]);
                }
            }
            {
                const float* wk = Wsh1 + k * 8 * 8;
                const float gt[8] = { t0.x, t0.y, t0.z, t0.w, t1.x, t1.y, t1.z, t1.w };
#pragma unroll
                for (int ci = 0; ci < 8; ci++) {
                    u64 g2 = pack2(gt[ci]);
                    const u64* wr = (const u64*)(wk + ci * 8);
#pragma unroll
                    for (int cc = 0; cc < 4; cc++) fma2(acc1[cc], g2, wr[cc]);
                }
            }
        }
        a0 = na0; a1 = na1; t0 = nt0; t1 = nt1;
        sv = nv;
    }

    float t[8];
#pragma unroll
    for (int q = 0; q < 4; q++) {
        float2 v = unpack2(acc1[q]);
        t[2 * q]     = fmaxf(v.x + b11[2 * q], 0.f);
        t[2 * q + 1] = fmaxf(v.y + b11[2 * q + 1], 0.f);
    }

    u64 acc2[8];
#pragma unroll
    for (int c = 0; c < 8; c++) acc2[c] = 0ull;
#pragma unroll
    for (int ci = 0; ci < 8; ci++) {
        u64 g2 = pack2(t[ci]);
        const u64* wr = (const u64*)(Wsh2 + ci * 16);
#pragma unroll
        for (int cc = 0; cc < 8; cc++) fma2(acc2[cc], g2, wr[cc]);
    }

    float* op = ob + (size_t)p * 32;
#pragma unroll
    for (int q = 0; q < 4; q++) {
        float2 v0 = unpack2(acc0[2 * q]);
        float2 v1 = unpack2(acc0[2 * q + 1]);
        float4 o = make_float4(v0.x + b01[4 * q], v0.y + b01[4 * q + 1],
                               v1.x + b01[4 * q + 2], v1.y + b01[4 * q + 3]);
        float4 r = *(const float4*)(Rin + (size_t)p * 32 + 4 * q);
        o.x += r.x; o.y += r.y; o.z += r.z; o.w += r.w;
        *(float4*)(op + 4 * q) = o;
    }
#pragma unroll
    for (int q = 0; q < 4; q++) {
        float2 v0 = unpack2(acc2[2 * q]);
        float2 v1 = unpack2(acc2[2 * q + 1]);
        float4 o = make_float4(v0.x + b12[4 * q], v0.y + b12[4 * q + 1],
                               v1.x + b12[4 * q + 2], v1.y + b12[4 * q + 3]);
        float4 r = *(const float4*)(Rin + (size_t)p * 32 + 16 + 4 * q);
        o.x += r.x; o.y += r.y; o.z += r.z; o.w += r.w;
        *(float4*)(op + 16 + 4 * q) = o;
    }
}

template<bool CVT>
__global__ void add_kernel(const float* __restrict__ a, const float* __restrict__ b,
                           float* __restrict__ o, long long n4)
{
    long long i = blockIdx.x * (long long)blockDim.x + threadIdx.x;
    if (i < n4) {
        float4 x = ((const float4*)a)[i];
        float4 y = ((const float4*)b)[i];
        x.x += y.x; x.y += y.y; x.z += y.z; x.w += y.w;
        if (CVT) {
            x.x = rna_tf32(x.x); x.y = rna_tf32(x.y);
            x.z = rna_tf32(x.z); x.w = rna_tf32(x.w);
        }
        ((float4*)o)[i] = x;
    }
}

// ---------------------------------------------------------------------------
template<int K, int CIN, int COUT, int OS, int PIPE, bool RELU, bool CVTOUT,
         bool FUSEPW, int CK>
static void launch_tf32(const float* X, const int* idxT, const float* Wf,
                        const float* B, float* out,
                        const float* Wp, const float* Bp, float* Tout, int Nout)
{
    constexpr int SMEM = PIPE * (128 * CIN + (CIN / 8) * (COUT / 8) * 64) * 4;
    auto kfn = tf32_conv<K, CIN, COUT, OS, PIPE, RELU, CVTOUT, FUSEPW, CK>;
    cudaFuncSetAttribute(kfn, cudaFuncAttributeMaxDynamicSharedMemorySize, SMEM);
    int grid = (Nout + 127) / 128;
    kfn<<<grid, 128, SMEM>>>(X, idxT, Wf, B, out, Wp, Bp, Tout, Nout);
}

extern "C" void kernel_launch(void* const* d_in, const int* in_sizes, int n_in,
                              void* d_out, int out_size)
{
    const float* x_feat = (const float*)d_in[0];
    const float* f1_ref = (const float*)d_in[1];
    const float* w1   = (const float*)d_in[2];
    const float* b1   = (const float*)d_in[3];
    const float* wd   = (const float*)d_in[4];
    const float* bd   = (const float*)d_in[5];
    const float* rw00 = (const float*)d_in[6];
    const float* rb00 = (const float*)d_in[7];
    const float* rw01 = (const float*)d_in[8];
    const float* rb01 = (const float*)d_in[9];
    const float* rw10 = (const float*)d_in[10];
    const float* rb10 = (const float*)d_in[11];
    const float* rw11 = (const float*)d_in[12];
    const float* rb11 = (const float*)d_in[13];
    const float* rw12 = (const float*)d_in[14];
    const float* rb12 = (const float*)d_in[15];
    const float* w4   = (const float*)d_in[16];
    const float* b4   = (const float*)d_in[17];
    const int* idx1 = (const int*)d_in[18];
    const int* idxd = (const int*)d_in[19];
    const int* idx2 = (const int*)d_in[20];

    int N  = in_sizes[0] / 64;
    int N2 = in_sizes[19] / 8;

    float *X, *F1, *D0, *D1, *AT8;
    float *WF1, *WFd, *WF0, *WF4, *WFp;
    int *iT1, *iT2, *iTd;
    cudaGetSymbolAddress((void**)&X,   g_X);
    cudaGetSymbolAddress((void**)&F1,  g_F1);
    cudaGetSymbolAddress((void**)&D0,  g_D0);
    cudaGetSymbolAddress((void**)&D1,  g_D1);
    cudaGetSymbolAddress((void**)&AT8, g_AT8);
    cudaGetSymbolAddress((void**)&iT1, g_iT1);
    cudaGetSymbolAddress((void**)&iT2, g_iT2);
    cudaGetSymbolAddress((void**)&iTd, g_iTd);
    cudaGetSymbolAddress((void**)&WF1, g_WF1);
    cudaGetSymbolAddress((void**)&WFd, g_WFd);
    cudaGetSymbolAddress((void**)&WF0, g_WF0);
    cudaGetSymbolAddress((void**)&WF4, g_WF4);
    cudaGetSymbolAddress((void**)&WFp, g_WFp);

    long long n4 = (long long)N * 16;

    // launches 0..2: deps of the center GEMM
    add_kernel<true><<<(int)((n4 + 255) / 256), 256>>>(x_feat, f1_ref, X, n4); // 0
    transpose_idx<<<(N + 255) / 256, 256>>>(idx1, iT1, N, 27);                 // 1
    prep_wfrag<<<(27 * 4096 + 255) / 256, 256>>>(w1, WF1, 27, 64, 64);         // 2

    // launch 3: conv1 center (k=13): F1 = X @ W13 + b1  (dense, no relu yet)
    launch_tf32<1, 64, 64, 64, 2, false, false, false, 0>(
        X, iT1 + (size_t)13 * N, WF1 + (size_t)13 * 4096, b1, F1,
        nullptr, nullptr, nullptr, N);

    // conv1 non-center: compacted gather-GEMM-scatter into F1
    zero_cnt_kernel<<<1, 32>>>();
    build_pairs<<<(N + 255) / 256, 256>>>(iT1, N, 27, 13);
    {
        constexpr int SMEM = (128 * 64 + 4096) * 4;
        auto kfn = compact_gemm<64, 64>;
        cudaFuncSetAttribute(kfn, cudaFuncAttributeMaxDynamicSharedMemorySize, SMEM);
        dim3 grid((N + 127) / 128, 27);
        kfn<<<grid, 128, SMEM>>>(X, WF1, N, F1);
    }

    // relu + tf32-round F1
    relu_cvt_kernel<<<(int)((n4 + 255) / 256), 256>>>(F1, n4);

    // down: dense K=8, 64->32, relu
    transpose_idx<<<(N2 + 255) / 256, 256>>>(idxd, iTd, N2, 8);
    prep_wfrag<<<(8 * 2048 + 255) / 256, 256>>>(wd, WFd, 8, 64, 32);
    launch_tf32<8, 64, 32, 32, 2, true, false, false, 0>(
        F1, iTd, WFd, bd, D0, nullptr, nullptr, nullptr, N2);

    // coarse-lattice prep
    transpose_idx<<<(N2 + 255) / 256, 256>>>(idx2, iT2, N2, 27);
    prep_wfrag<<<(81 * 256 + 255) / 256, 256>>>(rw00, WF0, 81, 32, 8);
    prep_wfrag<<<(27 * 256 + 255) / 256, 256>>>(w4,   WF4, 27, 32, 8);
    prep_wfrag<<<(3 * 256 + 255) / 256, 256>>>(rw10,  WFp, 3,  32, 8);

    float* bufs[2] = { D0, D1 };
    for (int i = 0; i < 3; i++) {
        float* in = bufs[i & 1];
        float* ob = bufs[(i + 1) & 1];

        // K1: AT8[:, :8] = relu(conv27(in, rw00)); AT8[:, 8:] = relu(in @ rw10)
        launch_tf32<27, 32, 8, 16, 3, true, false, true, 13>(
            in, iT2, WF0 + (size_t)i * 27 * 256, rb00 + i * 8, AT8,
            WFp + (size_t)i * 256, rb10 + i * 8, AT8 + 8, N2);

        // K2: full inception tail (rw01 conv + rw11 conv + rw12 pw + resid)
        spconv_tail<27><<<(N2 + 255) / 256, 256>>>(
            AT8, iT2,
            rw01 + (size_t)i * 27 * 8 * 16, rb01 + i * 16,
            rw11 + (size_t)i * 27 * 8 * 8,  rb11 + i * 8,
            rw12 + (size_t)i * 8 * 16,      rb12 + i * 16,
            in, ob, N2);
    }

    // enc4: K=27, 32->8, no relu, straight to output
    launch_tf32<27, 32, 8, 8, 3, false, false, false, 0>(
        bufs[1], iT2, WF4, b4, (float*)d_out, nullptr, nullptr, nullptr, N2);
}

// round 11
// speedup vs baseline: 1.1741x; 1.0650x over previous
#include <cuda_runtime.h>
#include <cuda_bf16.h>

typedef unsigned long long u64;
typedef unsigned int u32;

#define MAXN 250048

// Scratch (allocation-free rule: __device__ globals)
__device__ float g_X  [(size_t)MAXN * 64];
__device__ float g_F1 [(size_t)MAXN * 64];
__device__ float g_D0 [(size_t)MAXN * 32];
__device__ float g_D1 [(size_t)MAXN * 32];
__device__ float g_AT8[(size_t)MAXN * 16];   // interleaved A8 | T8
__device__ int   g_iT1[(size_t)MAXN * 27];
__device__ int   g_iT2[(size_t)MAXN * 27];
__device__ int   g_iTd[(size_t)MAXN * 8];
__device__ int   g_src[(size_t)MAXN * 27];   // compacted pair lists (per-k segments)
__device__ int   g_dst[(size_t)MAXN * 27];
__device__ int   g_cnt[32];
// fragment-packed tf32 weights
__device__ float g_WF1[27 * 4096];   // conv1
__device__ float g_WFd[8 * 2048];    // down
__device__ float g_WF0[81 * 256];    // rw00 (3 blocks as K=81)
__device__ float g_WF4[27 * 256];    // enc4
__device__ float g_WFp[3 * 256];     // rw10 pointwise

__device__ __forceinline__ u64 pack2(float x) {
    u64 r;
    asm("mov.b64 %0, {%1, %1};" : "=l"(r) : "r"(__float_as_uint(x)));
    return r;
}
__device__ __forceinline__ void fma2(u64& acc, u64 a, u64 b) {
    asm("fma.rn.f32x2 %0, %1, %2, %0;" : "+l"(acc) : "l"(a), "l"(b));
}
__device__ __forceinline__ float2 unpack2(u64 v) {
    float2 r;
    r.x = __uint_as_float((u32)(v & 0xffffffffull));
    r.y = __uint_as_float((u32)(v >> 32));
    return r;
}
__device__ __forceinline__ u32 smem_u32(const void* p) {
    return (u32)__cvta_generic_to_shared(p);
}
__device__ __forceinline__ void cpasync16(u32 dst, const void* src, u32 ssz) {
    asm volatile("cp.async.ca.shared.global [%0], [%1], 16, %2;\n"
                 :: "r"(dst), "l"(src), "r"(ssz));
}
__device__ __forceinline__ void cp_commit() {
    asm volatile("cp.async.commit_group;\n");
}
template<int N>
__device__ __forceinline__ void cp_wait() {
    asm volatile("cp.async.wait_group %0;\n" :: "n"(N));
}
__device__ __forceinline__ float rna_tf32(float x) {
    u32 y;
    asm("cvt.rna.tf32.f32 %0, %1;" : "=r"(y) : "f"(x));
    return __uint_as_float(y);
}
__device__ __forceinline__ void mma8(float4& d, const float* a, float2 b) {
    asm("mma.sync.aligned.m16n8k8.row.col.f32.tf32.tf32.f32 "
        "{%0,%1,%2,%3}, {%4,%5,%6,%7}, {%8,%9}, {%0,%1,%2,%3};"
        : "+f"(d.x), "+f"(d.y), "+f"(d.z), "+f"(d.w)
        : "r"(__float_as_uint(a[0])), "r"(__float_as_uint(a[1])),
          "r"(__float_as_uint(a[2])), "r"(__float_as_uint(a[3])),
          "r"(__float_as_uint(b.x)),  "r"(__float_as_uint(b.y)));
}
__device__ __forceinline__ void red2(float* p, float x, float y) {
    asm volatile("red.global.add.v2.f32 [%0], {%1, %2};"
                 :: "l"(p), "f"(x), "f"(y) : "memory");
}

// ---------------------------------------------------------------------------
__global__ void zero_cnt_kernel() {
    if (threadIdx.x < 32) g_cnt[threadIdx.x] = 0;
}

// smem-tiled transpose: coalesced loads, conflict-free stride-K smem reads
__global__ void transpose256(const int* __restrict__ in, int* __restrict__ outT,
                             int Npt, int K)
{
    extern __shared__ int tile[];
    const int tid = threadIdx.x;
    const int p0 = blockIdx.x * 256;
    const int total = 256 * K;
    const long long base = (long long)p0 * K;
    const long long lim = (long long)Npt * K;
    for (int e = tid; e < total; e += 256)
        if (base + e < lim) tile[e] = in[base + e];
    __syncthreads();
    const int p = p0 + tid;
    if (p < Npt)
        for (int k = 0; k < K; k++)
            outT[(size_t)k * Npt + p] = tile[tid * K + k];
}

// Warp-aggregated per-k pair compaction (skips skipK; center handled densely).
__global__ void build_pairs(const int* __restrict__ idxT, int Npt, int K, int skipK)
{
    int p = blockIdx.x * 256 + threadIdx.x;
    int lane = threadIdx.x & 31;
    for (int k = 0; k < K; k++) {
        if (k == skipK) continue;
        int s = (p < Npt) ? idxT[(size_t)k * Npt + p] : -1;
        bool valid = (s >= 0);
        u32 m = __ballot_sync(0xffffffffu, valid);
        if (!m) continue;
        int leader = __ffs(m) - 1;
        int base = 0;
        if (lane == leader) base = atomicAdd(&g_cnt[k], __popc(m));
        base = __shfl_sync(0xffffffffu, base, leader);
        if (valid) {
            int off = base + __popc(m & ((1u << lane) - 1));
            g_src[(size_t)k * Npt + off] = s;
            g_dst[(size_t)k * Npt + off] = p;
        }
    }
}

// W[k][ci][co] fp32 -> tf32 B-fragment order
__global__ void prep_wfrag(const float* __restrict__ W, float* __restrict__ Wf,
                           int K, int CIN, int COUT)
{
    int Q = CIN / 8, NT = COUT / 8;
    int total = K * Q * NT * 64;
    int e = blockIdx.x * 256 + threadIdx.x;
    if (e >= total) return;
    int j = e & 1;
    int lane = (e >> 1) & 31;
    int r = e >> 6;
    int nt = r % NT; r /= NT;
    int q = r % Q;  int k = r / Q;
    int ci = q * 8 + (lane & 3) + 4 * j;
    int co = nt * 8 + (lane >> 2);
    Wf[e] = rna_tf32(W[((size_t)k * CIN + ci) * COUT + co]);
}

// ---------------------------------------------------------------------------
// Fused conv1-center: X = tf32(x_feat + f1_ref) (written back), then
// F1 = X @ W13 + b1  (dense identity-map GEMM).  256 thr / 128 points,
// 8 warps x 1 m-tile -> 50% occupancy at 48KB smem.
// ---------------------------------------------------------------------------
__global__ void __launch_bounds__(256)
center_fused(const float* __restrict__ xa, const float* __restrict__ xb,
             const float* __restrict__ Wf, const float* __restrict__ Bb,
             float* __restrict__ Xout, float* __restrict__ F1, int N)
{
    extern __shared__ float sm[];
    float* A  = sm;              // 128 x 64
    float* Wk = sm + 128 * 64;   // 4096

    const int tid = threadIdx.x, wid = tid >> 5, lane = tid & 31;
    const int r7 = lane >> 2;
    const int cl = lane & 3;
    const int pt = tid >> 1, h = tid & 1;
    const int p0 = blockIdx.x * 128;
    const int gp = p0 + pt;

    for (int e = tid; e < 1024; e += 256)
        ((float4*)Wk)[e] = ((const float4*)Wf)[e];

    if (gp < N) {
        const float4* ra = (const float4*)(xa + (size_t)gp * 64) + h * 8;
        const float4* rb = (const float4*)(xb + (size_t)gp * 64) + h * 8;
        float4* xo = (float4*)(Xout + (size_t)gp * 64) + h * 8;
#pragma unroll
        for (int g = 0; g < 8; g++) {
            float4 va = ra[g], vb = rb[g];
            float4 v = make_float4(rna_tf32(va.x + vb.x), rna_tf32(va.y + vb.y),
                                   rna_tf32(va.z + vb.z), rna_tf32(va.w + vb.w));
            xo[g] = v;
            int c4 = h * 8 + g;
            *(float4*)(A + pt * 64 + ((c4 ^ (pt & 7)) << 2)) = v;
        }
    }
    __syncthreads();

    float4 acc[8];
#pragma unroll
    for (int nt = 0; nt < 8; nt++) acc[nt] = make_float4(0.f, 0.f, 0.f, 0.f);

    const int rl = wid * 16 + r7;
#pragma unroll
    for (int q = 0; q < 8; q++) {
        const int c4a = ((2 * q) ^ r7) << 2;
        const int c4b = ((2 * q + 1) ^ r7) << 2;
        float a[4];
        a[0] = A[rl * 64 + c4a + cl];
        a[1] = A[(rl + 8) * 64 + c4a + cl];
        a[2] = A[rl * 64 + c4b + cl];
        a[3] = A[(rl + 8) * 64 + c4b + cl];
#pragma unroll
        for (int nt = 0; nt < 8; nt++) {
            float2 b = *(const float2*)(Wk + ((q * 8 + nt) * 32 + lane) * 2);
            mma8(acc[nt], a, b);
        }
    }

    const int rlo = p0 + wid * 16 + r7;
    const int rhi = rlo + 8;
#pragma unroll
    for (int nt = 0; nt < 8; nt++) {
        const int c0 = nt * 8 + 2 * cl;
        const float b0 = Bb[c0], b1 = Bb[c0 + 1];
        if (rlo < N) *(float2*)(F1 + (size_t)rlo * 64 + c0)
            = make_float2(acc[nt].x + b0, acc[nt].y + b1);
        if (rhi < N) *(float2*)(F1 + (size_t)rhi * 64 + c0)
            = make_float2(acc[nt].z + b0, acc[nt].w + b1);
    }
}

// ---------------------------------------------------------------------------
// Dense tf32 mma.sync gather-GEMM sparse conv (128 pts/CTA, NTHR threads).
// NTHR=256: 8 warps x 1 m-tile, gather threads stage half-rows (2x occupancy).
// PIPE-deep cp.async ring; per-stage idx register-prefetched one iter ahead.
// ---------------------------------------------------------------------------
template<int K, int CIN, int COUT, int OS, int PIPE, int NTHR, bool RELU,
         bool CVTOUT, bool FUSEPW, int CK>
__global__ void __launch_bounds__(NTHR)
tf32_conv(const float* __restrict__ X, const int* __restrict__ idxT,
          const float* __restrict__ Wf, const float* __restrict__ Bb,
          float* __restrict__ out,
          const float* __restrict__ Wp, const float* __restrict__ Bp,
          float* __restrict__ Tout, int Nout)
{
    constexpr int NW   = NTHR / 32;
    constexpr int MT   = 8 / NW;          // m16 tiles per warp (128 rows total)
    constexpr int HALV = NTHR / 128;
    constexpr int Q    = CIN / 8;
    constexpr int NT   = COUT / 8;
    constexpr int ASTG = 128 * CIN;
    constexpr int WSTG = Q * NT * 64;
    constexpr int STG  = ASTG + WSTG;
    constexpr int C4U  = CIN / 4;
    constexpr int C4H  = C4U / HALV;

    extern __shared__ float sm[];

    const int tid = threadIdx.x, wid = tid >> 5, lane = tid & 31;
    const int r7 = lane >> 2;
    const int cl = lane & 3;
    const int pt = tid / HALV;
    const int h  = tid % HALV;
    const int p0 = blockIdx.x * 128;
    const int gp = p0 + pt;
    const bool pv = gp < Nout;

    float2 b10[FUSEPW ? Q : 1];
    if (FUSEPW) {
#pragma unroll
        for (int q = 0; q < Q; q++)
            b10[q] = *(const float2*)(Wp + (q * 32 + lane) * 2);
    }

    auto ldidx = [&](int k) -> int {
        return (pv && k < K) ? idxT[(size_t)k * Nout + gp] : -1;
    };

    auto prefetch = [&](int k, int src) {
        const int s = k % PIPE;
        const float* srow = X + (size_t)(src >= 0 ? src : 0) * CIN;
        u32 ssz = (src >= 0) ? 16u : 0u;
        u32 base = smem_u32(sm + s * STG) + (u32)pt * (CIN * 4);
#pragma unroll
        for (int c4h = 0; c4h < C4H; c4h++) {
            const int c4 = h * C4H + c4h;
            cpasync16(base + ((u32)(c4 ^ (pt & 7)) << 4), srow + 4 * c4, ssz);
        }
        const float4* wg = (const float4*)(Wf + (size_t)k * WSTG);
        u32 wdst = smem_u32(sm + s * STG + ASTG);
        for (int e = tid; e < WSTG / 4; e += NTHR)
            cpasync16(wdst + 16u * e, wg + e, 16);
    };

#pragma unroll
    for (int k = 0; k < PIPE - 1; k++) {
        if (k < K) prefetch(k, ldidx(k));
        cp_commit();
    }
    int src_nxt = ldidx(PIPE - 1);

    float4 acc[MT][NT];
#pragma unroll
    for (int m = 0; m < MT; m++)
#pragma unroll
        for (int nt = 0; nt < NT; nt++)
            acc[m][nt] = make_float4(0.f, 0.f, 0.f, 0.f);
    float4 acc2[MT];
#pragma unroll
    for (int m = 0; m < MT; m++) acc2[m] = make_float4(0.f, 0.f, 0.f, 0.f);

#pragma unroll 1
    for (int k = 0; k < K; k++) {
        __syncthreads();
        if (k + PIPE - 1 < K) prefetch(k + PIPE - 1, src_nxt);
        src_nxt = ldidx(k + PIPE);
        cp_commit();
        cp_wait<PIPE - 1>();
        __syncthreads();

        const float* A  = sm + (k % PIPE) * STG;
        const float* Wk = A + ASTG;

#pragma unroll
        for (int q = 0; q < Q; q++) {
            const int c4a = ((2 * q) ^ r7) << 2;
            const int c4b = ((2 * q + 1) ^ r7) << 2;
            float a[MT][4];
#pragma unroll
            for (int m = 0; m < MT; m++) {
                const int rl = wid * (MT * 16) + m * 16 + r7;
                a[m][0] = A[rl * CIN + c4a + cl];
                a[m][1] = A[(rl + 8) * CIN + c4a + cl];
                a[m][2] = A[rl * CIN + c4b + cl];
                a[m][3] = A[(rl + 8) * CIN + c4b + cl];
            }
#pragma unroll
            for (int nt = 0; nt < NT; nt++) {
                float2 b = *(const float2*)(Wk + ((q * NT + nt) * 32 + lane) * 2);
#pragma unroll
                for (int m = 0; m < MT; m++) mma8(acc[m][nt], a[m], b);
            }
            if (FUSEPW && k == CK) {
#pragma unroll
                for (int m = 0; m < MT; m++) mma8(acc2[m], a[m], b10[q]);
            }
        }
    }

#pragma unroll
    for (int m = 0; m < MT; m++) {
        const int rlo = p0 + wid * (MT * 16) + m * 16 + r7;
        const int rhi = rlo + 8;
#pragma unroll
        for (int nt = 0; nt < NT; nt++) {
            const int c0 = nt * 8 + 2 * cl;
            const float b0 = Bb[c0], b1 = Bb[c0 + 1];
            float2 v0 = make_float2(acc[m][nt].x + b0, acc[m][nt].y + b1);
            float2 v1 = make_float2(acc[m][nt].z + b0, acc[m][nt].w + b1);
            if (RELU) {
                v0.x = fmaxf(v0.x, 0.f); v0.y = fmaxf(v0.y, 0.f);
                v1.x = fmaxf(v1.x, 0.f); v1.y = fmaxf(v1.y, 0.f);
            }
            if (CVTOUT) {
                v0.x = rna_tf32(v0.x); v0.y = rna_tf32(v0.y);
                v1.x = rna_tf32(v1.x); v1.y = rna_tf32(v1.y);
            }
            if (rlo < Nout) *(float2*)(out + (size_t)rlo * OS + c0) = v0;
            if (rhi < Nout) *(float2*)(out + (size_t)rhi * OS + c0) = v1;
        }
        if (FUSEPW) {
            const int c0 = 2 * cl;
            const float b0 = Bp[c0], b1 = Bp[c0 + 1];
            float2 v0 = make_float2(fmaxf(acc2[m].x + b0, 0.f),
                                    fmaxf(acc2[m].y + b1, 0.f));
            float2 v1 = make_float2(fmaxf(acc2[m].z + b0, 0.f),
                                    fmaxf(acc2[m].w + b1, 0.f));
            if (rlo < Nout) *(float2*)(Tout + (size_t)rlo * OS + c0) = v0;
            if (rhi < Nout) *(float2*)(Tout + (size_t)rhi * OS + c0) = v1;
        }
    }
}

// ---------------------------------------------------------------------------
// Compacted per-k gather-GEMM-scatter (conv1 non-center), v2 reductions.
// ---------------------------------------------------------------------------
template<int CIN, int COUT>
__global__ void __launch_bounds__(128)
compact_gemm(const float* __restrict__ X, const float* __restrict__ Wf,
             int segStride, float* __restrict__ out)
{
    constexpr int Q    = CIN / 8;
    constexpr int NT   = COUT / 8;
    constexpr int WSTG = Q * NT * 64;
    constexpr int C4U  = CIN / 4;

    const int k = blockIdx.y;
    const int n = g_cnt[k];
    const int r0 = blockIdx.x * 128;
    if (r0 >= n) return;

    extern __shared__ float sm[];
    float* A  = sm;
    float* Wk = sm + 128 * CIN;

    const int tid = threadIdx.x, wid = tid >> 5, lane = tid & 31;
    const int r7 = lane >> 2;
    const int cl = lane & 3;

    const u32 ab = smem_u32(A);
    const u32 wb = smem_u32(Wk);

    {
        int row = r0 + tid;
        int s = (row < n) ? g_src[(size_t)k * segStride + row] : -1;
        const float* srow = X + (size_t)(s >= 0 ? s : 0) * CIN;
        u32 ssz = (s >= 0) ? 16u : 0u;
        u32 base = ab + (u32)tid * (CIN * 4);
#pragma unroll
        for (int c4 = 0; c4 < C4U; c4++)
            cpasync16(base + ((u32)(c4 ^ (tid & 7)) << 4), srow + 4 * c4, ssz);
        const float4* wg = (const float4*)(Wf + (size_t)k * WSTG);
        for (int e = tid; e < WSTG / 4; e += 128)
            cpasync16(wb + 16u * e, wg + e, 16);
    }
    cp_commit();
    cp_wait<0>();
    __syncthreads();

    float4 acc[2][NT];
#pragma unroll
    for (int m = 0; m < 2; m++)
#pragma unroll
        for (int nt = 0; nt < NT; nt++)
            acc[m][nt] = make_float4(0.f, 0.f, 0.f, 0.f);

#pragma unroll
    for (int q = 0; q < Q; q++) {
        const int c4a = ((2 * q) ^ r7) << 2;
        const int c4b = ((2 * q + 1) ^ r7) << 2;
        float a[2][4];
#pragma unroll
        for (int m = 0; m < 2; m++) {
            const int rl = wid * 32 + m * 16 + r7;
            a[m][0] = A[rl * CIN + c4a + cl];
            a[m][1] = A[(rl + 8) * CIN + c4a + cl];
            a[m][2] = A[rl * CIN + c4b + cl];
            a[m][3] = A[(rl + 8) * CIN + c4b + cl];
        }
#pragma unroll
        for (int nt = 0; nt < NT; nt++) {
            float2 b = *(const float2*)(Wk + ((q * NT + nt) * 32 + lane) * 2);
            mma8(acc[0][nt], a[0], b);
            mma8(acc[1][nt], a[1], b);
        }
    }

#pragma unroll
    for (int m = 0; m < 2; m++) {
        const int rlo = r0 + wid * 32 + m * 16 + r7;
        const int rhi = rlo + 8;
        int dlo = (rlo < n) ? g_dst[(size_t)k * segStride + rlo] : -1;
        int dhi = (rhi < n) ? g_dst[(size_t)k * segStride + rhi] : -1;
#pragma unroll
        for (int nt = 0; nt < NT; nt++) {
            const int c0 = nt * 8 + 2 * cl;
            if (dlo >= 0)
                red2(out + (size_t)dlo * COUT + c0, acc[m][nt].x, acc[m][nt].y);
            if (dhi >= 0)
                red2(out + (size_t)dhi * COUT + c0, acc[m][nt].z, acc[m][nt].w);
        }
    }
}

// relu + tf32 round, in place
__global__ void relu_cvt_kernel(float* __restrict__ buf, long long n4)
{
    long long i = blockIdx.x * (long long)blockDim.x + threadIdx.x;
    if (i < n4) {
        float4 x = ((float4*)buf)[i];
        x.x = rna_tf32(fmaxf(x.x, 0.f)); x.y = rna_tf32(fmaxf(x.y, 0.f));
        x.z = rna_tf32(fmaxf(x.z, 0.f)); x.w = rna_tf32(fmaxf(x.w, 0.f));
        ((float4*)buf)[i] = x;
    }
}

// ---------------------------------------------------------------------------
// Fused inception tail (AT8 = [a8|t8] interleaved, stride 16) with validity skip
// ---------------------------------------------------------------------------
template<int K>
__global__ void __launch_bounds__(256)
spconv_tail(const float* __restrict__ AT8, const int* __restrict__ idxT,
            const float* __restrict__ W01, const float* __restrict__ b01,
            const float* __restrict__ W11, const float* __restrict__ b11,
            const float* __restrict__ W12, const float* __restrict__ b12,
            const float* __restrict__ Rin, float* __restrict__ ob, int Nout)
{
    __shared__ float Wsh0[K * 8 * 16];
    __shared__ float Wsh1[K * 8 * 8];
    __shared__ float Wsh2[8 * 16];
    for (int e = threadIdx.x; e < K * 8 * 16; e += 256) Wsh0[e] = W01[e];
    for (int e = threadIdx.x; e < K * 8 * 8; e += 256)  Wsh1[e] = W11[e];
    if (threadIdx.x < 128) Wsh2[threadIdx.x] = W12[threadIdx.x];
    __syncthreads();

    const int p = blockIdx.x * 256 + threadIdx.x;
    if (p >= Nout) return;

    u64 acc0[8], acc1[4];
#pragma unroll
    for (int c = 0; c < 8; c++) acc0[c] = 0ull;
#pragma unroll
    for (int c = 0; c < 4; c++) acc1[c] = 0ull;

    const float4 z4 = make_float4(0.f, 0.f, 0.f, 0.f);
    int s_nxt = (K > 1) ? idxT[(size_t)Nout + p] : -1;
    int s0 = idxT[p];
    bool sv = (s0 >= 0);
    float4 a0 = z4, a1 = z4, t0 = z4, t1 = z4;
    if (sv) {
        const float4* r = (const float4*)(AT8 + (size_t)s0 * 16);
        a0 = r[0]; a1 = r[1]; t0 = r[2]; t1 = r[3];
    }

#pragma unroll 1
    for (int k = 0; k < K; k++) {
        float4 na0 = z4, na1 = z4, nt0 = z4, nt1 = z4;
        bool nv = false;
        if (k + 1 < K) {
            if (s_nxt >= 0) {
                nv = true;
                const float4* r = (const float4*)(AT8 + (size_t)s_nxt * 16);
                na0 = r[0]; na1 = r[1]; nt0 = r[2]; nt1 = r[3];
            }
            s_nxt = (k + 2 < K) ? idxT[(size_t)(k + 2) * Nout + p] : -1;
        }
        if (sv) {
            {
                const float* wk = Wsh0 + k * 8 * 16;
                const float ga[8] = { a0.x, a0.y, a0.z, a0.w, a1.x, a1.y, a1.z, a1.w };
#pragma unroll
                for (int ci = 0; ci < 8; ci++) {
                    u64 g2 = pack2(ga[ci]);
                    const u64* wr = (const u64*)(wk + ci * 16);
#pragma unroll
                    for (int cc = 0; cc < 8; cc++) fma2(acc0[cc], g2, wr[cc]);
                }
            }
            {
                const float* wk = Wsh1 + k * 8 * 8;
                const float gt[8] = { t0.x, t0.y, t0.z, t0.w, t1.x, t1.y, t1.z, t1.w };
#pragma unroll
                for (int ci = 0; ci < 8; ci++) {
                    u64 g2 = pack2(gt[ci]);
                    const u64* wr = (const u64*)(wk + ci * 8);
#pragma unroll
                    for (int cc = 0; cc < 4; cc++) fma2(acc1[cc], g2, wr[cc]);
                }
            }
        }
        a0 = na0; a1 = na1; t0 = nt0; t1 = nt1;
        sv = nv;
    }

    float t[8];
#pragma unroll
    for (int q = 0; q < 4; q++) {
        float2 v = unpack2(acc1[q]);
        t[2 * q]     = fmaxf(v.x + b11[2 * q], 0.f);
        t[2 * q + 1] = fmaxf(v.y + b11[2 * q + 1], 0.f);
    }

    u64 acc2[8];
#pragma unroll
    for (int c = 0; c < 8; c++) acc2[c] = 0ull;
#pragma unroll
    for (int ci = 0; ci < 8; ci++) {
        u64 g2 = pack2(t[ci]);
        const u64* wr = (const u64*)(Wsh2 + ci * 16);
#pragma unroll
        for (int cc = 0; cc < 8; cc++) fma2(acc2[cc], g2, wr[cc]);
    }

    float* op = ob + (size_t)p * 32;
#pragma unroll
    for (int q = 0; q < 4; q++) {
        float2 v0 = unpack2(acc0[2 * q]);
        float2 v1 = unpack2(acc0[2 * q + 1]);
        float4 o = make_float4(v0.x + b01[4 * q], v0.y + b01[4 * q + 1],
                               v1.x + b01[4 * q + 2], v1.y + b01[4 * q + 3]);
        float4 r = *(const float4*)(Rin + (size_t)p * 32 + 4 * q);
        o.x += r.x; o.y += r.y; o.z += r.z; o.w += r.w;
        *(float4*)(op + 4 * q) = o;
    }
#pragma unroll
    for (int q = 0; q < 4; q++) {
        float2 v0 = unpack2(acc2[2 * q]);
        float2 v1 = unpack2(acc2[2 * q + 1]);
        float4 o = make_float4(v0.x + b12[4 * q], v0.y + b12[4 * q + 1],
                               v1.x + b12[4 * q + 2], v1.y + b12[4 * q + 3]);
        float4 r = *(const float4*)(Rin + (size_t)p * 32 + 16 + 4 * q);
        o.x += r.x; o.y += r.y; o.z += r.z; o.w += r.w;
        *(float4*)(op + 16 + 4 * q) = o;
    }
}

// ---------------------------------------------------------------------------
template<int K, int CIN, int COUT, int OS, int PIPE, int NTHR, bool RELU,
         bool CVTOUT, bool FUSEPW, int CK>
static void launch_tf32(const float* X, const int* idxT, const float* Wf,
                        const float* B, float* out,
                        const float* Wp, const float* Bp, float* Tout, int Nout)
{
    constexpr int SMEM = PIPE * (128 * CIN + (CIN / 8) * (COUT / 8) * 64) * 4;
    auto kfn = tf32_conv<K, CIN, COUT, OS, PIPE, NTHR, RELU, CVTOUT, FUSEPW, CK>;
    cudaFuncSetAttribute(kfn, cudaFuncAttributeMaxDynamicSharedMemorySize, SMEM);
    int grid = (Nout + 127) / 128;
    kfn<<<grid, NTHR, SMEM>>>(X, idxT, Wf, B, out, Wp, Bp, Tout, Nout);
}

extern "C" void kernel_launch(void* const* d_in, const int* in_sizes, int n_in,
                              void* d_out, int out_size)
{
    const float* x_feat = (const float*)d_in[0];
    const float* f1_ref = (const float*)d_in[1];
    const float* w1   = (const float*)d_in[2];
    const float* b1   = (const float*)d_in[3];
    const float* wd   = (const float*)d_in[4];
    const float* bd   = (const float*)d_in[5];
    const float* rw00 = (const float*)d_in[6];
    const float* rb00 = (const float*)d_in[7];
    const float* rw01 = (const float*)d_in[8];
    const float* rb01 = (const float*)d_in[9];
    const float* rw10 = (const float*)d_in[10];
    const float* rb10 = (const float*)d_in[11];
    const float* rw11 = (const float*)d_in[12];
    const float* rb11 = (const float*)d_in[13];
    const float* rw12 = (const float*)d_in[14];
    const float* rb12 = (const float*)d_in[15];
    const float* w4   = (const float*)d_in[16];
    const float* b4   = (const float*)d_in[17];
    const int* idx1 = (const int*)d_in[18];
    const int* idxd = (const int*)d_in[19];
    const int* idx2 = (const int*)d_in[20];

    int N  = in_sizes[0] / 64;
    int N2 = in_sizes[19] / 8;

    float *X, *F1, *D0, *D1, *AT8;
    float *WF1, *WFd, *WF0, *WF4, *WFp;
    int *iT1, *iT2, *iTd;
    cudaGetSymbolAddress((void**)&X,   g_X);
    cudaGetSymbolAddress((void**)&F1,  g_F1);
    cudaGetSymbolAddress((void**)&D0,  g_D0);
    cudaGetSymbolAddress((void**)&D1,  g_D1);
    cudaGetSymbolAddress((void**)&AT8, g_AT8);
    cudaGetSymbolAddress((void**)&iT1, g_iT1);
    cudaGetSymbolAddress((void**)&iT2, g_iT2);
    cudaGetSymbolAddress((void**)&iTd, g_iTd);
    cudaGetSymbolAddress((void**)&WF1, g_WF1);
    cudaGetSymbolAddress((void**)&WFd, g_WFd);
    cudaGetSymbolAddress((void**)&WF0, g_WF0);
    cudaGetSymbolAddress((void**)&WF4, g_WF4);
    cudaGetSymbolAddress((void**)&WFp, g_WFp);

    long long n4 = (long long)N * 16;

    // launches 0..2: deps
    transpose256<<<(N + 255) / 256, 256, 27 * 256 * 4>>>(idx1, iT1, N, 27);  // 0
    prep_wfrag<<<(27 * 4096 + 255) / 256, 256>>>(w1, WF1, 27, 64, 64);       // 1
    zero_cnt_kernel<<<1, 32>>>();                                            // 2

    // launch 3 (ncu capture slot): fused add + center GEMM
    {
        constexpr int SMEM = (128 * 64 + 4096) * 4;
        cudaFuncSetAttribute(center_fused,
                             cudaFuncAttributeMaxDynamicSharedMemorySize, SMEM);
        center_fused<<<(N + 127) / 128, 256, SMEM>>>(
            x_feat, f1_ref, WF1 + (size_t)13 * 4096, b1, X, F1, N);
    }

    // conv1 non-center: compacted gather-GEMM-scatter into F1
    build_pairs<<<(N + 255) / 256, 256>>>(iT1, N, 27, 13);
    {
        constexpr int SMEM = (128 * 64 + 4096) * 4;
        auto kfn = compact_gemm<64, 64>;
        cudaFuncSetAttribute(kfn, cudaFuncAttributeMaxDynamicSharedMemorySize, SMEM);
        dim3 grid((N + 127) / 128, 27);
        kfn<<<grid, 128, SMEM>>>(X, WF1, N, F1);
    }

    // relu + tf32-round F1
    relu_cvt_kernel<<<(int)((n4 + 255) / 256), 256>>>(F1, n4);

    // down: dense K=8, 64->32, relu (256 thr)
    transpose256<<<(N2 + 255) / 256, 256, 8 * 256 * 4>>>(idxd, iTd, N2, 8);
    prep_wfrag<<<(8 * 2048 + 255) / 256, 256>>>(wd, WFd, 8, 64, 32);
    launch_tf32<8, 64, 32, 32, 2, 256, true, false, false, 0>(
        F1, iTd, WFd, bd, D0, nullptr, nullptr, nullptr, N2);

    // coarse-lattice prep
    transpose256<<<(N2 + 255) / 256, 256, 27 * 256 * 4>>>(idx2, iT2, N2, 27);
    prep_wfrag<<<(81 * 256 + 255) / 256, 256>>>(rw00, WF0, 81, 32, 8);
    prep_wfrag<<<(27 * 256 + 255) / 256, 256>>>(w4,   WF4, 27, 32, 8);
    prep_wfrag<<<(3 * 256 + 255) / 256, 256>>>(rw10,  WFp, 3,  32, 8);

    float* bufs[2] = { D0, D1 };
    for (int i = 0; i < 3; i++) {
        float* in = bufs[i & 1];
        float* ob = bufs[(i + 1) & 1];

        // K1: AT8[:, :8] = relu(conv27(in, rw00)); AT8[:, 8:] = relu(in @ rw10)
        launch_tf32<27, 32, 8, 16, 3, 256, true, false, true, 13>(
            in, iT2, WF0 + (size_t)i * 27 * 256, rb00 + i * 8, AT8,
            WFp + (size_t)i * 256, rb10 + i * 8, AT8 + 8, N2);

        // K2: full inception tail (rw01 conv + rw11 conv + rw12 pw + resid)
        spconv_tail<27><<<(N2 + 255) / 256, 256>>>(
            AT8, iT2,
            rw01 + (size_t)i * 27 * 8 * 16, rb01 + i * 16,
            rw11 + (size_t)i * 27 * 8 * 8,  rb11 + i * 8,
            rw12 + (size_t)i * 8 * 16,      rb12 + i * 16,
            in, ob, N2);
    }

    // enc4: K=27, 32->8, no relu, straight to output
    launch_tf32<27, 32, 8, 8, 3, 256, false, false, false, 0>(
        bufs[1], iT2, WF4, b4, (float*)d_out, nullptr, nullptr, nullptr, N2);
}

// round 13
// speedup vs baseline: 1.1923x; 1.0155x over previous
#include <cuda_runtime.h>
#include <cuda_bf16.h>

typedef unsigned long long u64;
typedef unsigned int u32;

#define MAXN 250048

// Scratch (allocation-free rule: __device__ globals)
__device__ float g_F1 [(size_t)MAXN * 64];
__device__ float g_D0 [(size_t)MAXN * 32];
__device__ float g_D1 [(size_t)MAXN * 32];
__device__ float g_AT8[(size_t)MAXN * 16];   // interleaved A8 | T8
__device__ int   g_iT2[(size_t)MAXN * 27];
__device__ int   g_iTd[(size_t)MAXN * 8];
__device__ int   g_src[(size_t)MAXN * 27];   // compacted pair lists (per-k segments)
__device__ int   g_dst[(size_t)MAXN * 27];
__device__ int   g_cnt[32];
// fragment-packed tf32 weights
__device__ float g_WF1[27 * 4096];   // conv1
__device__ float g_WFd[8 * 2048];    // down
__device__ float g_WF0[81 * 256];    // rw00 (3 blocks as K=81)
__device__ float g_WF4[27 * 256];    // enc4
__device__ float g_WFp[3 * 256];     // rw10 pointwise

__device__ __forceinline__ u64 pack2(float x) {
    u64 r;
    asm("mov.b64 %0, {%1, %1};" : "=l"(r) : "r"(__float_as_uint(x)));
    return r;
}
__device__ __forceinline__ void fma2(u64& acc, u64 a, u64 b) {
    asm("fma.rn.f32x2 %0, %1, %2, %0;" : "+l"(acc) : "l"(a), "l"(b));
}
__device__ __forceinline__ float2 unpack2(u64 v) {
    float2 r;
    r.x = __uint_as_float((u32)(v & 0xffffffffull));
    r.y = __uint_as_float((u32)(v >> 32));
    return r;
}
__device__ __forceinline__ u32 smem_u32(const void* p) {
    return (u32)__cvta_generic_to_shared(p);
}
__device__ __forceinline__ void cpasync16(u32 dst, const void* src, u32 ssz) {
    asm volatile("cp.async.ca.shared.global [%0], [%1], 16, %2;\n"
                 :: "r"(dst), "l"(src), "r"(ssz));
}
__device__ __forceinline__ void cp_commit() {
    asm volatile("cp.async.commit_group;\n");
}
template<int N>
__device__ __forceinline__ void cp_wait() {
    asm volatile("cp.async.wait_group %0;\n" :: "n"(N));
}
__device__ __forceinline__ float rna_tf32(float x) {
    u32 y;
    asm("cvt.rna.tf32.f32 %0, %1;" : "=r"(y) : "f"(x));
    return __uint_as_float(y);
}
__device__ __forceinline__ void mma8(float4& d, const float* a, float2 b) {
    asm("mma.sync.aligned.m16n8k8.row.col.f32.tf32.tf32.f32 "
        "{%0,%1,%2,%3}, {%4,%5,%6,%7}, {%8,%9}, {%0,%1,%2,%3};"
        : "+f"(d.x), "+f"(d.y), "+f"(d.z), "+f"(d.w)
        : "r"(__float_as_uint(a[0])), "r"(__float_as_uint(a[1])),
          "r"(__float_as_uint(a[2])), "r"(__float_as_uint(a[3])),
          "r"(__float_as_uint(b.x)),  "r"(__float_as_uint(b.y)));
}
__device__ __forceinline__ void red2(float* p, float x, float y) {
    asm volatile("red.global.add.v2.f32 [%0], {%1, %2};"
                 :: "l"(p), "f"(x), "f"(y) : "memory");
}

// ---------------------------------------------------------------------------
__global__ void zero_cnt_kernel() {
    if (threadIdx.x < 32) g_cnt[threadIdx.x] = 0;
}

// smem-tiled transpose: coalesced loads, conflict-free stride-K smem reads
__global__ void transpose256(const int* __restrict__ in, int* __restrict__ outT,
                             int Npt, int K)
{
    extern __shared__ int tile[];
    const int tid = threadIdx.x;
    const int p0 = blockIdx.x * 256;
    const int total = 256 * K;
    const long long base = (long long)p0 * K;
    const long long lim = (long long)Npt * K;
    for (int e = tid; e < total; e += 256)
        if (base + e < lim) tile[e] = in[base + e];
    __syncthreads();
    const int p = p0 + tid;
    if (p < Npt)
        for (int k = 0; k < K; k++)
            outT[(size_t)k * Npt + p] = tile[tid * K + k];
}

// Fused: coalesced idx1 staging + warp-aggregated per-k pair compaction.
// No transposed index is materialized.  (K=27, skip center k=13.)
__global__ void build_pairs_fused(const int* __restrict__ idx1, int Npt)
{
    __shared__ int tile[256 * 27];
    const int tid = threadIdx.x;
    const int lane = tid & 31;
    const int p0 = blockIdx.x * 256;
    const long long base = (long long)p0 * 27;
    const long long lim = (long long)Npt * 27;
    for (int e = tid; e < 256 * 27; e += 256)
        if (base + e < lim) tile[e] = idx1[base + e];
    __syncthreads();
    const int p = p0 + tid;
    for (int k = 0; k < 27; k++) {
        if (k == 13) continue;
        int s = (p < Npt) ? tile[tid * 27 + k] : -1;
        bool valid = (s >= 0);
        u32 m = __ballot_sync(0xffffffffu, valid);
        if (!m) continue;
        int leader = __ffs(m) - 1;
        int bs = 0;
        if (lane == leader) bs = atomicAdd(&g_cnt[k], __popc(m));
        bs = __shfl_sync(0xffffffffu, bs, leader);
        if (valid) {
            int off = bs + __popc(m & ((1u << lane) - 1));
            g_src[(size_t)k * Npt + off] = s;
            g_dst[(size_t)k * Npt + off] = p;
        }
    }
}

// W[k][ci][co] fp32 -> tf32 B-fragment order
__global__ void prep_wfrag(const float* __restrict__ W, float* __restrict__ Wf,
                           int K, int CIN, int COUT)
{
    int Q = CIN / 8, NT = COUT / 8;
    int total = K * Q * NT * 64;
    int e = blockIdx.x * 256 + threadIdx.x;
    if (e >= total) return;
    int j = e & 1;
    int lane = (e >> 1) & 31;
    int r = e >> 6;
    int nt = r % NT; r /= NT;
    int q = r % Q;  int k = r / Q;
    int ci = q * 8 + (lane & 3) + 4 * j;
    int co = nt * 8 + (lane >> 2);
    Wf[e] = rna_tf32(W[((size_t)k * CIN + ci) * COUT + co]);
}

// ---------------------------------------------------------------------------
// Fused conv1-center: A = tf32(x_feat + f1_ref) staged in smem (never written
// to global), then F1 = A @ W13 + b1.  256 thr / 128 points.
// ---------------------------------------------------------------------------
__global__ void __launch_bounds__(256)
center_fused(const float* __restrict__ xa, const float* __restrict__ xb,
             const float* __restrict__ Wf, const float* __restrict__ Bb,
             float* __restrict__ F1, int N)
{
    extern __shared__ float sm[];
    float* A  = sm;              // 128 x 64
    float* Wk = sm + 128 * 64;   // 4096

    const int tid = threadIdx.x, wid = tid >> 5, lane = tid & 31;
    const int r7 = lane >> 2;
    const int cl = lane & 3;
    const int pt = tid >> 1, h = tid & 1;
    const int p0 = blockIdx.x * 128;
    const int gp = p0 + pt;

    for (int e = tid; e < 1024; e += 256)
        ((float4*)Wk)[e] = ((const float4*)Wf)[e];

    if (gp < N) {
        const float4* ra = (const float4*)(xa + (size_t)gp * 64) + h * 8;
        const float4* rb = (const float4*)(xb + (size_t)gp * 64) + h * 8;
#pragma unroll
        for (int g = 0; g < 8; g++) {
            float4 va = ra[g], vb = rb[g];
            float4 v = make_float4(rna_tf32(va.x + vb.x), rna_tf32(va.y + vb.y),
                                   rna_tf32(va.z + vb.z), rna_tf32(va.w + vb.w));
            int c4 = h * 8 + g;
            *(float4*)(A + pt * 64 + ((c4 ^ (pt & 7)) << 2)) = v;
        }
    }
    __syncthreads();

    float4 acc[8];
#pragma unroll
    for (int nt = 0; nt < 8; nt++) acc[nt] = make_float4(0.f, 0.f, 0.f, 0.f);

    const int rl = wid * 16 + r7;
#pragma unroll
    for (int q = 0; q < 8; q++) {
        const int c4a = ((2 * q) ^ r7) << 2;
        const int c4b = ((2 * q + 1) ^ r7) << 2;
        float a[4];
        a[0] = A[rl * 64 + c4a + cl];
        a[1] = A[(rl + 8) * 64 + c4a + cl];
        a[2] = A[rl * 64 + c4b + cl];
        a[3] = A[(rl + 8) * 64 + c4b + cl];
#pragma unroll
        for (int nt = 0; nt < 8; nt++) {
            float2 b = *(const float2*)(Wk + ((q * 8 + nt) * 32 + lane) * 2);
            mma8(acc[nt], a, b);
        }
    }

    const int rlo = p0 + wid * 16 + r7;
    const int rhi = rlo + 8;
#pragma unroll
    for (int nt = 0; nt < 8; nt++) {
        const int c0 = nt * 8 + 2 * cl;
        const float b0 = Bb[c0], b1 = Bb[c0 + 1];
        if (rlo < N) *(float2*)(F1 + (size_t)rlo * 64 + c0)
            = make_float2(acc[nt].x + b0, acc[nt].y + b1);
        if (rhi < N) *(float2*)(F1 + (size_t)rhi * 64 + c0)
            = make_float2(acc[nt].z + b0, acc[nt].w + b1);
    }
}

// ---------------------------------------------------------------------------
// Dense tf32 mma.sync gather-GEMM sparse conv (128 pts/CTA, NTHR threads).
// PIPE-deep cp.async ring; per-stage idx register-prefetched one iter ahead.
// ---------------------------------------------------------------------------
template<int K, int CIN, int COUT, int OS, int PIPE, int NTHR, bool RELU,
         bool CVTOUT, bool FUSEPW, int CK>
__global__ void __launch_bounds__(NTHR)
tf32_conv(const float* __restrict__ X, const int* __restrict__ idxT,
          const float* __restrict__ Wf, const float* __restrict__ Bb,
          float* __restrict__ out,
          const float* __restrict__ Wp, const float* __restrict__ Bp,
          float* __restrict__ Tout, int Nout)
{
    constexpr int NW   = NTHR / 32;
    constexpr int MT   = 8 / NW;
    constexpr int HALV = NTHR / 128;
    constexpr int Q    = CIN / 8;
    constexpr int NT   = COUT / 8;
    constexpr int ASTG = 128 * CIN;
    constexpr int WSTG = Q * NT * 64;
    constexpr int STG  = ASTG + WSTG;
    constexpr int C4U  = CIN / 4;
    constexpr int C4H  = C4U / HALV;

    extern __shared__ float sm[];

    const int tid = threadIdx.x, wid = tid >> 5, lane = tid & 31;
    const int r7 = lane >> 2;
    const int cl = lane & 3;
    const int pt = tid / HALV;
    const int h  = tid % HALV;
    const int p0 = blockIdx.x * 128;
    const int gp = p0 + pt;
    const bool pv = gp < Nout;

    float2 b10[FUSEPW ? Q : 1];
    if (FUSEPW) {
#pragma unroll
        for (int q = 0; q < Q; q++)
            b10[q] = *(const float2*)(Wp + (q * 32 + lane) * 2);
    }

    auto ldidx = [&](int k) -> int {
        return (pv && k < K) ? idxT[(size_t)k * Nout + gp] : -1;
    };

    auto prefetch = [&](int k, int src) {
        const int s = k % PIPE;
        const float* srow = X + (size_t)(src >= 0 ? src : 0) * CIN;
        u32 ssz = (src >= 0) ? 16u : 0u;
        u32 base = smem_u32(sm + s * STG) + (u32)pt * (CIN * 4);
#pragma unroll
        for (int c4h = 0; c4h < C4H; c4h++) {
            const int c4 = h * C4H + c4h;
            cpasync16(base + ((u32)(c4 ^ (pt & 7)) << 4), srow + 4 * c4, ssz);
        }
        const float4* wg = (const float4*)(Wf + (size_t)k * WSTG);
        u32 wdst = smem_u32(sm + s * STG + ASTG);
        for (int e = tid; e < WSTG / 4; e += NTHR)
            cpasync16(wdst + 16u * e, wg + e, 16);
    };

#pragma unroll
    for (int k = 0; k < PIPE - 1; k++) {
        if (k < K) prefetch(k, ldidx(k));
        cp_commit();
    }
    int src_nxt = ldidx(PIPE - 1);

    float4 acc[MT][NT];
#pragma unroll
    for (int m = 0; m < MT; m++)
#pragma unroll
        for (int nt = 0; nt < NT; nt++)
            acc[m][nt] = make_float4(0.f, 0.f, 0.f, 0.f);
    float4 acc2[MT];
#pragma unroll
    for (int m = 0; m < MT; m++) acc2[m] = make_float4(0.f, 0.f, 0.f, 0.f);

#pragma unroll 1
    for (int k = 0; k < K; k++) {
        __syncthreads();
        if (k + PIPE - 1 < K) prefetch(k + PIPE - 1, src_nxt);
        src_nxt = ldidx(k + PIPE);
        cp_commit();
        cp_wait<PIPE - 1>();
        __syncthreads();

        const float* A  = sm + (k % PIPE) * STG;
        const float* Wk = A + ASTG;

#pragma unroll
        for (int q = 0; q < Q; q++) {
            const int c4a = ((2 * q) ^ r7) << 2;
            const int c4b = ((2 * q + 1) ^ r7) << 2;
            float a[MT][4];
#pragma unroll
            for (int m = 0; m < MT; m++) {
                const int rl = wid * (MT * 16) + m * 16 + r7;
                a[m][0] = A[rl * CIN + c4a + cl];
                a[m][1] = A[(rl + 8) * CIN + c4a + cl];
                a[m][2] = A[rl * CIN + c4b + cl];
                a[m][3] = A[(rl + 8) * CIN + c4b + cl];
            }
#pragma unroll
            for (int nt = 0; nt < NT; nt++) {
                float2 b = *(const float2*)(Wk + ((q * NT + nt) * 32 + lane) * 2);
#pragma unroll
                for (int m = 0; m < MT; m++) mma8(acc[m][nt], a[m], b);
            }
            if (FUSEPW && k == CK) {
#pragma unroll
                for (int m = 0; m < MT; m++) mma8(acc2[m], a[m], b10[q]);
            }
        }
    }

#pragma unroll
    for (int m = 0; m < MT; m++) {
        const int rlo = p0 + wid * (MT * 16) + m * 16 + r7;
        const int rhi = rlo + 8;
#pragma unroll
        for (int nt = 0; nt < NT; nt++) {
            const int c0 = nt * 8 + 2 * cl;
            const float b0 = Bb[c0], b1 = Bb[c0 + 1];
            float2 v0 = make_float2(acc[m][nt].x + b0, acc[m][nt].y + b1);
            float2 v1 = make_float2(acc[m][nt].z + b0, acc[m][nt].w + b1);
            if (RELU) {
                v0.x = fmaxf(v0.x, 0.f); v0.y = fmaxf(v0.y, 0.f);
                v1.x = fmaxf(v1.x, 0.f); v1.y = fmaxf(v1.y, 0.f);
            }
            if (CVTOUT) {
                v0.x = rna_tf32(v0.x); v0.y = rna_tf32(v0.y);
                v1.x = rna_tf32(v1.x); v1.y = rna_tf32(v1.y);
            }
            if (rlo < Nout) *(float2*)(out + (size_t)rlo * OS + c0) = v0;
            if (rhi < Nout) *(float2*)(out + (size_t)rhi * OS + c0) = v1;
        }
        if (FUSEPW) {
            const int c0 = 2 * cl;
            const float b0 = Bp[c0], b1 = Bp[c0 + 1];
            float2 v0 = make_float2(fmaxf(acc2[m].x + b0, 0.f),
                                    fmaxf(acc2[m].y + b1, 0.f));
            float2 v1 = make_float2(fmaxf(acc2[m].z + b0, 0.f),
                                    fmaxf(acc2[m].w + b1, 0.f));
            if (rlo < Nout) *(float2*)(Tout + (size_t)rlo * OS + c0) = v0;
            if (rhi < Nout) *(float2*)(Tout + (size_t)rhi * OS + c0) = v1;
        }
    }
}

// ---------------------------------------------------------------------------
// Compacted per-k gather-GEMM-scatter (conv1 non-center), grid-stride over
// row blocks.  Gathers xa+xb directly (tf32-rounded) — no X buffer.
// W[k] staged once per CTA.  v2 reductions into F1.
// ---------------------------------------------------------------------------
__global__ void __launch_bounds__(128)
compact_gemm64(const float* __restrict__ xa, const float* __restrict__ xb,
               const float* __restrict__ Wf, int segStride,
               float* __restrict__ out)
{
    constexpr int WSTG = 4096;
    const int k = blockIdx.y;
    const int n = g_cnt[k];
    if (blockIdx.x * 128 >= n) return;

    extern __shared__ float sm[];
    float* A  = sm;              // 128 x 64
    float* Wk = sm + 128 * 64;

    const int tid = threadIdx.x, wid = tid >> 5, lane = tid & 31;
    const int r7 = lane >> 2;
    const int cl = lane & 3;

    // stage W[k] once
    {
        const float4* wg = (const float4*)(Wf + (size_t)k * WSTG);
        u32 wb = smem_u32(Wk);
        for (int e = tid; e < WSTG / 4; e += 128)
            cpasync16(wb + 16u * e, wg + e, 16);
        cp_commit();
        cp_wait<0>();
    }

    for (int r0 = blockIdx.x * 128; r0 < n; r0 += gridDim.x * 128) {
        __syncthreads();   // previous iteration's MMA reads done
        {
            int row = r0 + tid;
            int s = (row < n) ? g_src[(size_t)k * segStride + row] : -1;
            const float4* ra = (const float4*)(xa + (size_t)(s >= 0 ? s : 0) * 64);
            const float4* rb = (const float4*)(xb + (size_t)(s >= 0 ? s : 0) * 64);
            float* arow = A + tid * 64;
#pragma unroll
            for (int c4 = 0; c4 < 16; c4++) {
                float4 v = make_float4(0.f, 0.f, 0.f, 0.f);
                if (s >= 0) {
                    float4 va = ra[c4], vb = rb[c4];
                    v = make_float4(rna_tf32(va.x + vb.x), rna_tf32(va.y + vb.y),
                                    rna_tf32(va.z + vb.z), rna_tf32(va.w + vb.w));
                }
                *(float4*)(arow + ((c4 ^ (tid & 7)) << 2)) = v;
            }
        }
        __syncthreads();

        float4 acc[2][8];
#pragma unroll
        for (int m = 0; m < 2; m++)
#pragma unroll
            for (int nt = 0; nt < 8; nt++)
                acc[m][nt] = make_float4(0.f, 0.f, 0.f, 0.f);

#pragma unroll
        for (int q = 0; q < 8; q++) {
            const int c4a = ((2 * q) ^ r7) << 2;
            const int c4b = ((2 * q + 1) ^ r7) << 2;
            float a[2][4];
#pragma unroll
            for (int m = 0; m < 2; m++) {
                const int rl = wid * 32 + m * 16 + r7;
                a[m][0] = A[rl * 64 + c4a + cl];
                a[m][1] = A[(rl + 8) * 64 + c4a + cl];
                a[m][2] = A[rl * 64 + c4b + cl];
                a[m][3] = A[(rl + 8) * 64 + c4b + cl];
            }
#pragma unroll
            for (int nt = 0; nt < 8; nt++) {
                float2 b = *(const float2*)(Wk + ((q * 8 + nt) * 32 + lane) * 2);
                mma8(acc[0][nt], a[0], b);
                mma8(acc[1][nt], a[1], b);
            }
        }

#pragma unroll
        for (int m = 0; m < 2; m++) {
            const int rlo = r0 + wid * 32 + m * 16 + r7;
            const int rhi = rlo + 8;
            int dlo = (rlo < n) ? g_dst[(size_t)k * segStride + rlo] : -1;
            int dhi = (rhi < n) ? g_dst[(size_t)k * segStride + rhi] : -1;
#pragma unroll
            for (int nt = 0; nt < 8; nt++) {
                const int c0 = nt * 8 + 2 * cl;
                if (dlo >= 0)
                    red2(out + (size_t)dlo * 64 + c0, acc[m][nt].x, acc[m][nt].y);
                if (dhi >= 0)
                    red2(out + (size_t)dhi * 64 + c0, acc[m][nt].z, acc[m][nt].w);
            }
        }
    }
}

// relu + tf32 round, in place
__global__ void relu_cvt_kernel(float* __restrict__ buf, long long n4)
{
    long long i = blockIdx.x * (long long)blockDim.x + threadIdx.x;
    if (i < n4) {
        float4 x = ((float4*)buf)[i];
        x.x = rna_tf32(fmaxf(x.x, 0.f)); x.y = rna_tf32(fmaxf(x.y, 0.f));
        x.z = rna_tf32(fmaxf(x.z, 0.f)); x.w = rna_tf32(fmaxf(x.w, 0.f));
        ((float4*)buf)[i] = x;
    }
}

// ---------------------------------------------------------------------------
// Fused inception tail (AT8 = [a8|t8] interleaved, stride 16) with validity skip
// ---------------------------------------------------------------------------
template<int K>
__global__ void __launch_bounds__(256)
spconv_tail(const float* __restrict__ AT8, const int* __restrict__ idxT,
            const float* __restrict__ W01, const float* __restrict__ b01,
            const float* __restrict__ W11, const float* __restrict__ b11,
            const float* __restrict__ W12, const float* __restrict__ b12,
            const float* __restrict__ Rin, float* __restrict__ ob, int Nout)
{
    __shared__ float Wsh0[K * 8 * 16];
    __shared__ float Wsh1[K * 8 * 8];
    __shared__ float Wsh2[8 * 16];
    for (int e = threadIdx.x; e < K * 8 * 16; e += 256) Wsh0[e] = W01[e];
    for (int e = threadIdx.x; e < K * 8 * 8; e += 256)  Wsh1[e] = W11[e];
    if (threadIdx.x < 128) Wsh2[threadIdx.x] = W12[threadIdx.x];
    __syncthreads();

    const int p = blockIdx.x * 256 + threadIdx.x;
    if (p >= Nout) return;

    u64 acc0[8], acc1[4];
#pragma unroll
    for (int c = 0; c < 8; c++) acc0[c] = 0ull;
#pragma unroll
    for (int c = 0; c < 4; c++) acc1[c] = 0ull;

    const float4 z4 = make_float4(0.f, 0.f, 0.f, 0.f);
    int s_nxt = (K > 1) ? idxT[(size_t)Nout + p] : -1;
    int s0 = idxT[p];
    bool sv = (s0 >= 0);
    float4 a0 = z4, a1 = z4, t0 = z4, t1 = z4;
    if (sv) {
        const float4* r = (const float4*)(AT8 + (size_t)s0 * 16);
        a0 = r[0]; a1 = r[1]; t0 = r[2]; t1 = r[3];
    }

#pragma unroll 1
    for (int k = 0; k < K; k++) {
        float4 na0 = z4, na1 = z4, nt0 = z4, nt1 = z4;
        bool nv = false;
        if (k + 1 < K) {
            if (s_nxt >= 0) {
                nv = true;
                const float4* r = (const float4*)(AT8 + (size_t)s_nxt * 16);
                na0 = r[0]; na1 = r[1]; nt0 = r[2]; nt1 = r[3];
            }
            s_nxt = (k + 2 < K) ? idxT[(size_t)(k + 2) * Nout + p] : -1;
        }
        if (sv) {
            {
                const float* wk = Wsh0 + k * 8 * 16;
                const float ga[8] = { a0.x, a0.y, a0.z, a0.w, a1.x, a1.y, a1.z, a1.w };
#pragma unroll
                for (int ci = 0; ci < 8; ci++) {
                    u64 g2 = pack2(ga[ci]);
                    const u64* wr = (const u64*)(wk + ci * 16);
#pragma unroll
                    for (int cc = 0; cc < 8; cc++) fma2(acc0[cc], g2, wr[cc]);
                }
            }
            {
                const float* wk = Wsh1 + k * 8 * 8;
                const float gt[8] = { t0.x, t0.y, t0.z, t0.w, t1.x, t1.y, t1.z, t1.w };
#pragma unroll
                for (int ci = 0; ci < 8; ci++) {
                    u64 g2 = pack2(gt[ci]);
                    const u64* wr = (const u64*)(wk + ci * 8);
#pragma unroll
                    for (int cc = 0; cc < 4; cc++) fma2(acc1[cc], g2, wr[cc]);
                }
            }
        }
        a0 = na0; a1 = na1; t0 = nt0; t1 = nt1;
        sv = nv;
    }

    float t[8];
#pragma unroll
    for (int q = 0; q < 4; q++) {
        float2 v = unpack2(acc1[q]);
        t[2 * q]     = fmaxf(v.x + b11[2 * q], 0.f);
        t[2 * q + 1] = fmaxf(v.y + b11[2 * q + 1], 0.f);
    }

    u64 acc2[8];
#pragma unroll
    for (int c = 0; c < 8; c++) acc2[c] = 0ull;
#pragma unroll
    for (int ci = 0; ci < 8; ci++) {
        u64 g2 = pack2(t[ci]);
        const u64* wr = (const u64*)(Wsh2 + ci * 16);
#pragma unroll
        for (int cc = 0; cc < 8; cc++) fma2(acc2[cc], g2, wr[cc]);
    }

    float* op = ob + (size_t)p * 32;
#pragma unroll
    for (int q = 0; q < 4; q++) {
        float2 v0 = unpack2(acc0[2 * q]);
        float2 v1 = unpack2(acc0[2 * q + 1]);
        float4 o = make_float4(v0.x + b01[4 * q], v0.y + b01[4 * q + 1],
                               v1.x + b01[4 * q + 2], v1.y + b01[4 * q + 3]);
        float4 r = *(const float4*)(Rin + (size_t)p * 32 + 4 * q);
        o.x += r.x; o.y += r.y; o.z += r.z; o.w += r.w;
        *(float4*)(op + 4 * q) = o;
    }
#pragma unroll
    for (int q = 0; q < 4; q++) {
        float2 v0 = unpack2(acc2[2 * q]);
        float2 v1 = unpack2(acc2[2 * q + 1]);
        float4 o = make_float4(v0.x + b12[4 * q], v0.y + b12[4 * q + 1],
                               v1.x + b12[4 * q + 2], v1.y + b12[4 * q + 3]);
        float4 r = *(const float4*)(Rin + (size_t)p * 32 + 16 + 4 * q);
        o.x += r.x; o.y += r.y; o.z += r.z; o.w += r.w;
        *(float4*)(op + 16 + 4 * q) = o;
    }
}

// ---------------------------------------------------------------------------
template<int K, int CIN, int COUT, int OS, int PIPE, int NTHR, bool RELU,
         bool CVTOUT, bool FUSEPW, int CK>
static void launch_tf32(const float* X, const int* idxT, const float* Wf,
                        const float* B, float* out,
                        const float* Wp, const float* Bp, float* Tout, int Nout)
{
    constexpr int SMEM = PIPE * (128 * CIN + (CIN / 8) * (COUT / 8) * 64) * 4;
    auto kfn = tf32_conv<K, CIN, COUT, OS, PIPE, NTHR, RELU, CVTOUT, FUSEPW, CK>;
    cudaFuncSetAttribute(kfn, cudaFuncAttributeMaxDynamicSharedMemorySize, SMEM);
    int grid = (Nout + 127) / 128;
    kfn<<<grid, NTHR, SMEM>>>(X, idxT, Wf, B, out, Wp, Bp, Tout, Nout);
}

extern "C" void kernel_launch(void* const* d_in, const int* in_sizes, int n_in,
                              void* d_out, int out_size)
{
    const float* x_feat = (const float*)d_in[0];
    const float* f1_ref = (const float*)d_in[1];
    const float* w1   = (const float*)d_in[2];
    const float* b1   = (const float*)d_in[3];
    const float* wd   = (const float*)d_in[4];
    const float* bd   = (const float*)d_in[5];
    const float* rw00 = (const float*)d_in[6];
    const float* rb00 = (const float*)d_in[7];
    const float* rw01 = (const float*)d_in[8];
    const float* rb01 = (const float*)d_in[9];
    const float* rw10 = (const float*)d_in[10];
    const float* rb10 = (const float*)d_in[11];
    const float* rw11 = (const float*)d_in[12];
    const float* rb11 = (const float*)d_in[13];
    const float* rw12 = (const float*)d_in[14];
    const float* rb12 = (const float*)d_in[15];
    const float* w4   = (const float*)d_in[16];
    const float* b4   = (const float*)d_in[17];
    const int* idx1 = (const int*)d_in[18];
    const int* idxd = (const int*)d_in[19];
    const int* idx2 = (const int*)d_in[20];

    int N  = in_sizes[0] / 64;
    int N2 = in_sizes[19] / 8;

    float *F1, *D0, *D1, *AT8;
    float *WF1, *WFd, *WF0, *WF4, *WFp;
    int *iT2, *iTd;
    cudaGetSymbolAddress((void**)&F1,  g_F1);
    cudaGetSymbolAddress((void**)&D0,  g_D0);
    cudaGetSymbolAddress((void**)&D1,  g_D1);
    cudaGetSymbolAddress((void**)&AT8, g_AT8);
    cudaGetSymbolAddress((void**)&iT2, g_iT2);
    cudaGetSymbolAddress((void**)&iTd, g_iTd);
    cudaGetSymbolAddress((void**)&WF1, g_WF1);
    cudaGetSymbolAddress((void**)&WFd, g_WFd);
    cudaGetSymbolAddress((void**)&WF0, g_WF0);
    cudaGetSymbolAddress((void**)&WF4, g_WF4);
    cudaGetSymbolAddress((void**)&WFp, g_WFp);

    long long n4 = (long long)N * 16;

    // prep for conv1
    zero_cnt_kernel<<<1, 32>>>();                                       // 0
    prep_wfrag<<<(27 * 4096 + 255) / 256, 256>>>(w1, WF1, 27, 64, 64);  // 1
    build_pairs_fused<<<(N + 255) / 256, 256>>>(idx1, N);               // 2

    // launch 3: fused add + center GEMM (A staged in smem only)
    {
        constexpr int SMEM = (128 * 64 + 4096) * 4;
        cudaFuncSetAttribute(center_fused,
                             cudaFuncAttributeMaxDynamicSharedMemorySize, SMEM);
        center_fused<<<(N + 127) / 128, 256, SMEM>>>(
            x_feat, f1_ref, WF1 + (size_t)13 * 4096, b1, F1, N);
    }

    // conv1 non-center: compacted gather-GEMM-scatter into F1 (grid-stride)
    {
        constexpr int SMEM = (128 * 64 + 4096) * 4;
        cudaFuncSetAttribute(compact_gemm64,
                             cudaFuncAttributeMaxDynamicSharedMemorySize, SMEM);
        dim3 grid((N + 1023) / 1024, 27);   // ~2x expected blocks; stride loop
        compact_gemm64<<<grid, 128, SMEM>>>(x_feat, f1_ref, WF1, N, F1);
    }

    // relu + tf32-round F1
    relu_cvt_kernel<<<(int)((n4 + 255) / 256), 256>>>(F1, n4);

    // down: dense K=8, 64->32, relu
    transpose256<<<(N2 + 255) / 256, 256, 8 * 256 * 4>>>(idxd, iTd, N2, 8);
    prep_wfrag<<<(8 * 2048 + 255) / 256, 256>>>(wd, WFd, 8, 64, 32);
    launch_tf32<8, 64, 32, 32, 2, 256, true, false, false, 0>(
        F1, iTd, WFd, bd, D0, nullptr, nullptr, nullptr, N2);

    // coarse-lattice prep
    transpose256<<<(N2 + 255) / 256, 256, 27 * 256 * 4>>>(idx2, iT2, N2, 27);
    prep_wfrag<<<(81 * 256 + 255) / 256, 256>>>(rw00, WF0, 81, 32, 8);
    prep_wfrag<<<(27 * 256 + 255) / 256, 256>>>(w4,   WF4, 27, 32, 8);
    prep_wfrag<<<(3 * 256 + 255) / 256, 256>>>(rw10,  WFp, 3,  32, 8);

    float* bufs[2] = { D0, D1 };
    for (int i = 0; i < 3; i++) {
        float* in = bufs[i & 1];
        float* ob = bufs[(i + 1) & 1];

        // K1: AT8[:, :8] = relu(conv27(in, rw00)); AT8[:, 8:] = relu(in @ rw10)
        launch_tf32<27, 32, 8, 16, 3, 256, true, false, true, 13>(
            in, iT2, WF0 + (size_t)i * 27 * 256, rb00 + i * 8, AT8,
            WFp + (size_t)i * 256, rb10 + i * 8, AT8 + 8, N2);

        // K2: full inception tail (rw01 conv + rw11 conv + rw12 pw + resid)
        spconv_tail<27><<<(N2 + 255) / 256, 256>>>(
            AT8, iT2,
            rw01 + (size_t)i * 27 * 8 * 16, rb01 + i * 16,
            rw11 + (size_t)i * 27 * 8 * 8,  rb11 + i * 8,
            rw12 + (size_t)i * 8 * 16,      rb12 + i * 16,
            in, ob, N2);
    }

    // enc4: K=27, 32->8, no relu, straight to output
    launch_tf32<27, 32, 8, 8, 3, 256, false, false, false, 0>(
        bufs[1], iT2, WF4, b4, (float*)d_out, nullptr, nullptr, nullptr, N2);
}

// round 15
// speedup vs baseline: 1.2011x; 1.0074x over previous
#include <cuda_runtime.h>
#include <cuda_bf16.h>

typedef unsigned long long u64;
typedef unsigned int u32;

#define MAXN 250048

// Scratch (allocation-free rule: __device__ globals)
__device__ float g_F1 [(size_t)MAXN * 64];
__device__ float g_D0 [(size_t)MAXN * 32];
__device__ float g_D1 [(size_t)MAXN * 32];
__device__ float g_AT8[(size_t)MAXN * 16];   // interleaved A8 | T8
__device__ int   g_iT2[(size_t)MAXN * 27];
__device__ int   g_src[(size_t)MAXN * 27];   // compacted pair lists (per-k segments)
__device__ int   g_dst[(size_t)MAXN * 27];
__device__ int   g_cnt[32];
// fragment-packed tf32 weights
__device__ float g_WF1[27 * 4096];   // conv1
__device__ float g_WFd[8 * 2048];    // down
__device__ float g_WF0[81 * 256];    // rw00 (3 blocks as K=81)
__device__ float g_WF4[27 * 256];    // enc4
__device__ float g_WFp[3 * 256];     // rw10 pointwise

__device__ __forceinline__ u64 pack2(float x) {
    u64 r;
    asm("mov.b64 %0, {%1, %1};" : "=l"(r) : "r"(__float_as_uint(x)));
    return r;
}
__device__ __forceinline__ void fma2(u64& acc, u64 a, u64 b) {
    asm("fma.rn.f32x2 %0, %1, %2, %0;" : "+l"(acc) : "l"(a), "l"(b));
}
__device__ __forceinline__ float2 unpack2(u64 v) {
    float2 r;
    r.x = __uint_as_float((u32)(v & 0xffffffffull));
    r.y = __uint_as_float((u32)(v >> 32));
    return r;
}
__device__ __forceinline__ u32 smem_u32(const void* p) {
    return (u32)__cvta_generic_to_shared(p);
}
__device__ __forceinline__ void cpasync16(u32 dst, const void* src, u32 ssz) {
    asm volatile("cp.async.ca.shared.global [%0], [%1], 16, %2;\n"
                 :: "r"(dst), "l"(src), "r"(ssz));
}
__device__ __forceinline__ void cp_commit() {
    asm volatile("cp.async.commit_group;\n");
}
template<int N>
__device__ __forceinline__ void cp_wait() {
    asm volatile("cp.async.wait_group %0;\n" :: "n"(N));
}
__device__ __forceinline__ float rna_tf32(float x) {
    u32 y;
    asm("cvt.rna.tf32.f32 %0, %1;" : "=r"(y) : "f"(x));
    return __uint_as_float(y);
}
__device__ __forceinline__ void mma8(float4& d, const float* a, float2 b) {
    asm("mma.sync.aligned.m16n8k8.row.col.f32.tf32.tf32.f32 "
        "{%0,%1,%2,%3}, {%4,%5,%6,%7}, {%8,%9}, {%0,%1,%2,%3};"
        : "+f"(d.x), "+f"(d.y), "+f"(d.z), "+f"(d.w)
        : "r"(__float_as_uint(a[0])), "r"(__float_as_uint(a[1])),
          "r"(__float_as_uint(a[2])), "r"(__float_as_uint(a[3])),
          "r"(__float_as_uint(b.x)),  "r"(__float_as_uint(b.y)));
}
__device__ __forceinline__ void red2(float* p, float x, float y) {
    asm volatile("red.global.add.v2.f32 [%0], {%1, %2};"
                 :: "l"(p), "f"(x), "f"(y) : "memory");
}

// ---------------------------------------------------------------------------
__global__ void zero_cnt_kernel() {
    if (threadIdx.x < 32) g_cnt[threadIdx.x] = 0;
}

// smem-tiled transpose: coalesced loads, conflict-free stride-K smem reads
__global__ void transpose256(const int* __restrict__ in, int* __restrict__ outT,
                             int Npt, int K)
{
    extern __shared__ int tile[];
    const int tid = threadIdx.x;
    const int p0 = blockIdx.x * 256;
    const int total = 256 * K;
    const long long base = (long long)p0 * K;
    const long long lim = (long long)Npt * K;
    for (int e = tid; e < total; e += 256)
        if (base + e < lim) tile[e] = in[base + e];
    __syncthreads();
    const int p = p0 + tid;
    if (p < Npt)
        for (int k = 0; k < K; k++)
            outT[(size_t)k * Npt + p] = tile[tid * K + k];
}

// Fused: coalesced idx staging + warp-aggregated per-k pair compaction.
// KK = kernel offsets, SKIPK = offset handled densely (-1 = none).
template<int KK, int SKIPK>
__global__ void build_pairs_fused(const int* __restrict__ idx, int Npt)
{
    extern __shared__ int tile[];
    const int tid = threadIdx.x;
    const int lane = tid & 31;
    const int p0 = blockIdx.x * 256;
    const long long base = (long long)p0 * KK;
    const long long lim = (long long)Npt * KK;
    for (int e = tid; e < 256 * KK; e += 256)
        if (base + e < lim) tile[e] = idx[base + e];
    __syncthreads();
    const int p = p0 + tid;
    for (int k = 0; k < KK; k++) {
        if (k == SKIPK) continue;
        int s = (p < Npt) ? tile[tid * KK + k] : -1;
        bool valid = (s >= 0);
        u32 m = __ballot_sync(0xffffffffu, valid);
        if (!m) continue;
        int leader = __ffs(m) - 1;
        int bs = 0;
        if (lane == leader) bs = atomicAdd(&g_cnt[k], __popc(m));
        bs = __shfl_sync(0xffffffffu, bs, leader);
        if (valid) {
            int off = bs + __popc(m & ((1u << lane) - 1));
            g_src[(size_t)k * Npt + off] = s;
            g_dst[(size_t)k * Npt + off] = p;
        }
    }
}

// W[k][ci][co] fp32 -> tf32 B-fragment order
__global__ void prep_wfrag(const float* __restrict__ W, float* __restrict__ Wf,
                           int K, int CIN, int COUT)
{
    int Q = CIN / 8, NT = COUT / 8;
    int total = K * Q * NT * 64;
    int e = blockIdx.x * 256 + threadIdx.x;
    if (e >= total) return;
    int j = e & 1;
    int lane = (e >> 1) & 31;
    int r = e >> 6;
    int nt = r % NT; r /= NT;
    int q = r % Q;  int k = r / Q;
    int ci = q * 8 + (lane & 3) + 4 * j;
    int co = nt * 8 + (lane >> 2);
    Wf[e] = rna_tf32(W[((size_t)k * CIN + ci) * COUT + co]);
}

// ---------------------------------------------------------------------------
// Fused conv1-center: A = tf32(x_feat + f1_ref) staged in smem only, then
// F1 = A @ W13 + b1.  256 thr / 128 points.
// ---------------------------------------------------------------------------
__global__ void __launch_bounds__(256)
center_fused(const float* __restrict__ xa, const float* __restrict__ xb,
             const float* __restrict__ Wf, const float* __restrict__ Bb,
             float* __restrict__ F1, int N)
{
    extern __shared__ float sm[];
    float* A  = sm;              // 128 x 64
    float* Wk = sm + 128 * 64;   // 4096

    const int tid = threadIdx.x, wid = tid >> 5, lane = tid & 31;
    const int r7 = lane >> 2;
    const int cl = lane & 3;
    const int pt = tid >> 1, h = tid & 1;
    const int p0 = blockIdx.x * 128;
    const int gp = p0 + pt;

    for (int e = tid; e < 1024; e += 256)
        ((float4*)Wk)[e] = ((const float4*)Wf)[e];

    if (gp < N) {
        const float4* ra = (const float4*)(xa + (size_t)gp * 64) + h * 8;
        const float4* rb = (const float4*)(xb + (size_t)gp * 64) + h * 8;
#pragma unroll
        for (int g = 0; g < 8; g++) {
            float4 va = ra[g], vb = rb[g];
            float4 v = make_float4(rna_tf32(va.x + vb.x), rna_tf32(va.y + vb.y),
                                   rna_tf32(va.z + vb.z), rna_tf32(va.w + vb.w));
            int c4 = h * 8 + g;
            *(float4*)(A + pt * 64 + ((c4 ^ (pt & 7)) << 2)) = v;
        }
    }
    __syncthreads();

    float4 acc[8];
#pragma unroll
    for (int nt = 0; nt < 8; nt++) acc[nt] = make_float4(0.f, 0.f, 0.f, 0.f);

    const int rl = wid * 16 + r7;
#pragma unroll
    for (int q = 0; q < 8; q++) {
        const int c4a = ((2 * q) ^ r7) << 2;
        const int c4b = ((2 * q + 1) ^ r7) << 2;
        float a[4];
        a[0] = A[rl * 64 + c4a + cl];
        a[1] = A[(rl + 8) * 64 + c4a + cl];
        a[2] = A[rl * 64 + c4b + cl];
        a[3] = A[(rl + 8) * 64 + c4b + cl];
#pragma unroll
        for (int nt = 0; nt < 8; nt++) {
            float2 b = *(const float2*)(Wk + ((q * 8 + nt) * 32 + lane) * 2);
            mma8(acc[nt], a, b);
        }
    }

    const int rlo = p0 + wid * 16 + r7;
    const int rhi = rlo + 8;
#pragma unroll
    for (int nt = 0; nt < 8; nt++) {
        const int c0 = nt * 8 + 2 * cl;
        const float b0 = Bb[c0], b1 = Bb[c0 + 1];
        if (rlo < N) *(float2*)(F1 + (size_t)rlo * 64 + c0)
            = make_float2(acc[nt].x + b0, acc[nt].y + b1);
        if (rhi < N) *(float2*)(F1 + (size_t)rhi * 64 + c0)
            = make_float2(acc[nt].z + b0, acc[nt].w + b1);
    }
}

// ---------------------------------------------------------------------------
// Dense tf32 mma.sync gather-GEMM sparse conv (128 pts/CTA, NTHR threads).
// PIPE-deep cp.async ring; per-stage idx register-prefetched one iter ahead.
// ---------------------------------------------------------------------------
template<int K, int CIN, int COUT, int OS, int PIPE, int NTHR, bool RELU,
         bool CVTOUT, bool FUSEPW, int CK>
__global__ void __launch_bounds__(NTHR)
tf32_conv(const float* __restrict__ X, const int* __restrict__ idxT,
          const float* __restrict__ Wf, const float* __restrict__ Bb,
          float* __restrict__ out,
          const float* __restrict__ Wp, const float* __restrict__ Bp,
          float* __restrict__ Tout, int Nout)
{
    constexpr int NW   = NTHR / 32;
    constexpr int MT   = 8 / NW;
    constexpr int HALV = NTHR / 128;
    constexpr int Q    = CIN / 8;
    constexpr int NT   = COUT / 8;
    constexpr int ASTG = 128 * CIN;
    constexpr int WSTG = Q * NT * 64;
    constexpr int STG  = ASTG + WSTG;
    constexpr int C4U  = CIN / 4;
    constexpr int C4H  = C4U / HALV;

    extern __shared__ float sm[];

    const int tid = threadIdx.x, wid = tid >> 5, lane = tid & 31;
    const int r7 = lane >> 2;
    const int cl = lane & 3;
    const int pt = tid / HALV;
    const int h  = tid % HALV;
    const int p0 = blockIdx.x * 128;
    const int gp = p0 + pt;
    const bool pv = gp < Nout;

    float2 b10[FUSEPW ? Q : 1];
    if (FUSEPW) {
#pragma unroll
        for (int q = 0; q < Q; q++)
            b10[q] = *(const float2*)(Wp + (q * 32 + lane) * 2);
    }

    auto ldidx = [&](int k) -> int {
        return (pv && k < K) ? idxT[(size_t)k * Nout + gp] : -1;
    };

    auto prefetch = [&](int k, int src) {
        const int s = k % PIPE;
        const float* srow = X + (size_t)(src >= 0 ? src : 0) * CIN;
        u32 ssz = (src >= 0) ? 16u : 0u;
        u32 base = smem_u32(sm + s * STG) + (u32)pt * (CIN * 4);
#pragma unroll
        for (int c4h = 0; c4h < C4H; c4h++) {
            const int c4 = h * C4H + c4h;
            cpasync16(base + ((u32)(c4 ^ (pt & 7)) << 4), srow + 4 * c4, ssz);
        }
        const float4* wg = (const float4*)(Wf + (size_t)k * WSTG);
        u32 wdst = smem_u32(sm + s * STG + ASTG);
        for (int e = tid; e < WSTG / 4; e += NTHR)
            cpasync16(wdst + 16u * e, wg + e, 16);
    };

#pragma unroll
    for (int k = 0; k < PIPE - 1; k++) {
        if (k < K) prefetch(k, ldidx(k));
        cp_commit();
    }
    int src_nxt = ldidx(PIPE - 1);

    float4 acc[MT][NT];
#pragma unroll
    for (int m = 0; m < MT; m++)
#pragma unroll
        for (int nt = 0; nt < NT; nt++)
            acc[m][nt] = make_float4(0.f, 0.f, 0.f, 0.f);
    float4 acc2[MT];
#pragma unroll
    for (int m = 0; m < MT; m++) acc2[m] = make_float4(0.f, 0.f, 0.f, 0.f);

#pragma unroll 1
    for (int k = 0; k < K; k++) {
        __syncthreads();
        if (k + PIPE - 1 < K) prefetch(k + PIPE - 1, src_nxt);
        src_nxt = ldidx(k + PIPE);
        cp_commit();
        cp_wait<PIPE - 1>();
        __syncthreads();

        const float* A  = sm + (k % PIPE) * STG;
        const float* Wk = A + ASTG;

#pragma unroll
        for (int q = 0; q < Q; q++) {
            const int c4a = ((2 * q) ^ r7) << 2;
            const int c4b = ((2 * q + 1) ^ r7) << 2;
            float a[MT][4];
#pragma unroll
            for (int m = 0; m < MT; m++) {
                const int rl = wid * (MT * 16) + m * 16 + r7;
                a[m][0] = A[rl * CIN + c4a + cl];
                a[m][1] = A[(rl + 8) * CIN + c4a + cl];
                a[m][2] = A[rl * CIN + c4b + cl];
                a[m][3] = A[(rl + 8) * CIN + c4b + cl];
            }
#pragma unroll
            for (int nt = 0; nt < NT; nt++) {
                float2 b = *(const float2*)(Wk + ((q * NT + nt) * 32 + lane) * 2);
#pragma unroll
                for (int m = 0; m < MT; m++) mma8(acc[m][nt], a[m], b);
            }
            if (FUSEPW && k == CK) {
#pragma unroll
                for (int m = 0; m < MT; m++) mma8(acc2[m], a[m], b10[q]);
            }
        }
    }

#pragma unroll
    for (int m = 0; m < MT; m++) {
        const int rlo = p0 + wid * (MT * 16) + m * 16 + r7;
        const int rhi = rlo + 8;
#pragma unroll
        for (int nt = 0; nt < NT; nt++) {
            const int c0 = nt * 8 + 2 * cl;
            const float b0 = Bb[c0], b1 = Bb[c0 + 1];
            float2 v0 = make_float2(acc[m][nt].x + b0, acc[m][nt].y + b1);
            float2 v1 = make_float2(acc[m][nt].z + b0, acc[m][nt].w + b1);
            if (RELU) {
                v0.x = fmaxf(v0.x, 0.f); v0.y = fmaxf(v0.y, 0.f);
                v1.x = fmaxf(v1.x, 0.f); v1.y = fmaxf(v1.y, 0.f);
            }
            if (CVTOUT) {
                v0.x = rna_tf32(v0.x); v0.y = rna_tf32(v0.y);
                v1.x = rna_tf32(v1.x); v1.y = rna_tf32(v1.y);
            }
            if (rlo < Nout) *(float2*)(out + (size_t)rlo * OS + c0) = v0;
            if (rhi < Nout) *(float2*)(out + (size_t)rhi * OS + c0) = v1;
        }
        if (FUSEPW) {
            const int c0 = 2 * cl;
            const float b0 = Bp[c0], b1 = Bp[c0 + 1];
            float2 v0 = make_float2(fmaxf(acc2[m].x + b0, 0.f),
                                    fmaxf(acc2[m].y + b1, 0.f));
            float2 v1 = make_float2(fmaxf(acc2[m].z + b0, 0.f),
                                    fmaxf(acc2[m].w + b1, 0.f));
            if (rlo < Nout) *(float2*)(Tout + (size_t)rlo * OS + c0) = v0;
            if (rhi < Nout) *(float2*)(Tout + (size_t)rhi * OS + c0) = v1;
        }
    }
}

// ---------------------------------------------------------------------------
// Compacted per-k gather-GEMM-scatter, CIN=64, grid-stride over row blocks.
// SUMIN: gather = tf32(xa+xb); else gather = xa rows directly.
// W[k] staged once per CTA.  v2 reductions into out (stride COUT).
// ---------------------------------------------------------------------------
template<int COUT, bool SUMIN>
__global__ void __launch_bounds__(128)
compact_gemm_t(const float* __restrict__ xa, const float* __restrict__ xb,
               const float* __restrict__ Wf, int segStride,
               float* __restrict__ out)
{
    constexpr int NT   = COUT / 8;
    constexpr int WSTG = COUT * 64;
    const int k = blockIdx.y;
    const int n = g_cnt[k];
    if (blockIdx.x * 128 >= n) return;

    extern __shared__ float sm[];
    float* A  = sm;              // 128 x 64
    float* Wk = sm + 128 * 64;

    const int tid = threadIdx.x, wid = tid >> 5, lane = tid & 31;
    const int r7 = lane >> 2;
    const int cl = lane & 3;

    {
        const float4* wg = (const float4*)(Wf + (size_t)k * WSTG);
        u32 wb = smem_u32(Wk);
        for (int e = tid; e < WSTG / 4; e += 128)
            cpasync16(wb + 16u * e, wg + e, 16);
        cp_commit();
        cp_wait<0>();
    }

    for (int r0 = blockIdx.x * 128; r0 < n; r0 += gridDim.x * 128) {
        __syncthreads();
        {
            int row = r0 + tid;
            int s = (row < n) ? g_src[(size_t)k * segStride + row] : -1;
            const float4* ra = (const float4*)(xa + (size_t)(s >= 0 ? s : 0) * 64);
            const float4* rb = (const float4*)(xb + (size_t)(s >= 0 ? s : 0) * 64);
            float* arow = A + tid * 64;
#pragma unroll
            for (int c4 = 0; c4 < 16; c4++) {
                float4 v = make_float4(0.f, 0.f, 0.f, 0.f);
                if (s >= 0) {
                    if (SUMIN) {
                        float4 va = ra[c4], vb = rb[c4];
                        v = make_float4(rna_tf32(va.x + vb.x), rna_tf32(va.y + vb.y),
                                        rna_tf32(va.z + vb.z), rna_tf32(va.w + vb.w));
                    } else {
                        v = ra[c4];
                    }
                }
                *(float4*)(arow + ((c4 ^ (tid & 7)) << 2)) = v;
            }
        }
        __syncthreads();

        float4 acc[2][NT];
#pragma unroll
        for (int m = 0; m < 2; m++)
#pragma unroll
            for (int nt = 0; nt < NT; nt++)
                acc[m][nt] = make_float4(0.f, 0.f, 0.f, 0.f);

#pragma unroll
        for (int q = 0; q < 8; q++) {
            const int c4a = ((2 * q) ^ r7) << 2;
            const int c4b = ((2 * q + 1) ^ r7) << 2;
            float a[2][4];
#pragma unroll
            for (int m = 0; m < 2; m++) {
                const int rl = wid * 32 + m * 16 + r7;
                a[m][0] = A[rl * 64 + c4a + cl];
                a[m][1] = A[(rl + 8) * 64 + c4a + cl];
                a[m][2] = A[rl * 64 + c4b + cl];
                a[m][3] = A[(rl + 8) * 64 + c4b + cl];
            }
#pragma unroll
            for (int nt = 0; nt < NT; nt++) {
                float2 b = *(const float2*)(Wk + ((q * NT + nt) * 32 + lane) * 2);
                mma8(acc[0][nt], a[0], b);
                mma8(acc[1][nt], a[1], b);
            }
        }

#pragma unroll
        for (int m = 0; m < 2; m++) {
            const int rlo = r0 + wid * 32 + m * 16 + r7;
            const int rhi = rlo + 8;
            int dlo = (rlo < n) ? g_dst[(size_t)k * segStride + rlo] : -1;
            int dhi = (rhi < n) ? g_dst[(size_t)k * segStride + rhi] : -1;
#pragma unroll
            for (int nt = 0; nt < NT; nt++) {
                const int c0 = nt * 8 + 2 * cl;
                if (dlo >= 0)
                    red2(out + (size_t)dlo * COUT + c0, acc[m][nt].x, acc[m][nt].y);
                if (dhi >= 0)
                    red2(out + (size_t)dhi * COUT + c0, acc[m][nt].z, acc[m][nt].w);
            }
        }
    }
}

// relu + tf32 round, in place (F1 epilogue)
__global__ void relu_cvt_kernel(float* __restrict__ buf, long long n4)
{
    long long i = blockIdx.x * (long long)blockDim.x + threadIdx.x;
    if (i < n4) {
        float4 x = ((float4*)buf)[i];
        x.x = rna_tf32(fmaxf(x.x, 0.f)); x.y = rna_tf32(fmaxf(x.y, 0.f));
        x.z = rna_tf32(fmaxf(x.z, 0.f)); x.w = rna_tf32(fmaxf(x.w, 0.f));
        ((float4*)buf)[i] = x;
    }
}

// bias + relu, 32-channel rows (down epilogue)
__global__ void bias_relu32(float* __restrict__ buf, const float* __restrict__ B,
                            long long n4)
{
    long long i = blockIdx.x * (long long)blockDim.x + threadIdx.x;
    if (i < n4) {
        float4 b = ((const float4*)B)[i & 7];   // 32 ch = 8 float4
        float4 x = ((float4*)buf)[i];
        x.x = fmaxf(x.x + b.x, 0.f); x.y = fmaxf(x.y + b.y, 0.f);
        x.z = fmaxf(x.z + b.z, 0.f); x.w = fmaxf(x.w + b.w, 0.f);
        ((float4*)buf)[i] = x;
    }
}

// ---------------------------------------------------------------------------
// Fused inception tail (AT8 = [a8|t8] interleaved, stride 16) with validity skip
// ---------------------------------------------------------------------------
template<int K>
__global__ void __launch_bounds__(256)
spconv_tail(const float* __restrict__ AT8, const int* __restrict__ idxT,
            const float* __restrict__ W01, const float* __restrict__ b01,
            const float* __restrict__ W11, const float* __restrict__ b11,
            const float* __restrict__ W12, const float* __restrict__ b12,
            const float* __restrict__ Rin, float* __restrict__ ob, int Nout)
{
    __shared__ float Wsh0[K * 8 * 16];
    __shared__ float Wsh1[K * 8 * 8];
    __shared__ float Wsh2[8 * 16];
    for (int e = threadIdx.x; e < K * 8 * 16; e += 256) Wsh0[e] = W01[e];
    for (int e = threadIdx.x; e < K * 8 * 8; e += 256)  Wsh1[e] = W11[e];
    if (threadIdx.x < 128) Wsh2[threadIdx.x] = W12[threadIdx.x];
    __syncthreads();

    const int p = blockIdx.x * 256 + threadIdx.x;
    if (p >= Nout) return;

    u64 acc0[8], acc1[4];
#pragma unroll
    for (int c = 0; c < 8; c++) acc0[c] = 0ull;
#pragma unroll
    for (int c = 0; c < 4; c++) acc1[c] = 0ull;

    const float4 z4 = make_float4(0.f, 0.f, 0.f, 0.f);
    int s_nxt = (K > 1) ? idxT[(size_t)Nout + p] : -1;
    int s0 = idxT[p];
    bool sv = (s0 >= 0);
    float4 a0 = z4, a1 = z4, t0 = z4, t1 = z4;
    if (sv) {
        const float4* r = (const float4*)(AT8 + (size_t)s0 * 16);
        a0 = r[0]; a1 = r[1]; t0 = r[2]; t1 = r[3];
    }

#pragma unroll 1
    for (int k = 0; k < K; k++) {
        float4 na0 = z4, na1 = z4, nt0 = z4, nt1 = z4;
        bool nv = false;
        if (k + 1 < K) {
            if (s_nxt >= 0) {
                nv = true;
                const float4* r = (const float4*)(AT8 + (size_t)s_nxt * 16);
                na0 = r[0]; na1 = r[1]; nt0 = r[2]; nt1 = r[3];
            }
            s_nxt = (k + 2 < K) ? idxT[(size_t)(k + 2) * Nout + p] : -1;
        }
        if (sv) {
            {
                const float* wk = Wsh0 + k * 8 * 16;
                const float ga[8] = { a0.x, a0.y, a0.z, a0.w, a1.x, a1.y, a1.z, a1.w };
#pragma unroll
                for (int ci = 0; ci < 8; ci++) {
                    u64 g2 = pack2(ga[ci]);
                    const u64* wr = (const u64*)(wk + ci * 16);
#pragma unroll
                    for (int cc = 0; cc < 8; cc++) fma2(acc0[cc], g2, wr[cc]);
                }
            }
            {
                const float* wk = Wsh1 + k * 8 * 8;
                const float gt[8] = { t0.x, t0.y, t0.z, t0.w, t1.x, t1.y, t1.z, t1.w };
#pragma unroll
                for (int ci = 0; ci < 8; ci++) {
                    u64 g2 = pack2(gt[ci]);
                    const u64* wr = (const u64*)(wk + ci * 8);
#pragma unroll
                    for (int cc = 0; cc < 4; cc++) fma2(acc1[cc], g2, wr[cc]);
                }
            }
        }
        a0 = na0; a1 = na1; t0 = nt0; t1 = nt1;
        sv = nv;
    }

    float t[8];
#pragma unroll
    for (int q = 0; q < 4; q++) {
        float2 v = unpack2(acc1[q]);
        t[2 * q]     = fmaxf(v.x + b11[2 * q], 0.f);
        t[2 * q + 1] = fmaxf(v.y + b11[2 * q + 1], 0.f);
    }

    u64 acc2[8];
#pragma unroll
    for (int c = 0; c < 8; c++) acc2[c] = 0ull;
#pragma unroll
    for (int ci = 0; ci < 8; ci++) {
        u64 g2 = pack2(t[ci]);
        const u64* wr = (const u64*)(Wsh2 + ci * 16);
#pragma unroll
        for (int cc = 0; cc < 8; cc++) fma2(acc2[cc], g2, wr[cc]);
    }

    float* op = ob + (size_t)p * 32;
#pragma unroll
    for (int q = 0; q < 4; q++) {
        float2 v0 = unpack2(acc0[2 * q]);
        float2 v1 = unpack2(acc0[2 * q + 1]);
        float4 o = make_float4(v0.x + b01[4 * q], v0.y + b01[4 * q + 1],
                               v1.x + b01[4 * q + 2], v1.y + b01[4 * q + 3]);
        float4 r = *(const float4*)(Rin + (size_t)p * 32 + 4 * q);
        o.x += r.x; o.y += r.y; o.z += r.z; o.w += r.w;
        *(float4*)(op + 4 * q) = o;
    }
#pragma unroll
    for (int q = 0; q < 4; q++) {
        float2 v0 = unpack2(acc2[2 * q]);
        float2 v1 = unpack2(acc2[2 * q + 1]);
        float4 o = make_float4(v0.x + b12[4 * q], v0.y + b12[4 * q + 1],
                               v1.x + b12[4 * q + 2], v1.y + b12[4 * q + 3]);
        float4 r = *(const float4*)(Rin + (size_t)p * 32 + 16 + 4 * q);
        o.x += r.x; o.y += r.y; o.z += r.z; o.w += r.w;
        *(float4*)(op + 16 + 4 * q) = o;
    }
}

// ---------------------------------------------------------------------------
template<int K, int CIN, int COUT, int OS, int PIPE, int NTHR, bool RELU,
         bool CVTOUT, bool FUSEPW, int CK>
static void launch_tf32(const float* X, const int* idxT, const float* Wf,
                        const float* B, float* out,
                        const float* Wp, const float* Bp, float* Tout, int Nout)
{
    constexpr int SMEM = PIPE * (128 * CIN + (CIN / 8) * (COUT / 8) * 64) * 4;
    auto kfn = tf32_conv<K, CIN, COUT, OS, PIPE, NTHR, RELU, CVTOUT, FUSEPW, CK>;
    cudaFuncSetAttribute(kfn, cudaFuncAttributeMaxDynamicSharedMemorySize, SMEM);
    int grid = (Nout + 127) / 128;
    kfn<<<grid, NTHR, SMEM>>>(X, idxT, Wf, B, out, Wp, Bp, Tout, Nout);
}

extern "C" void kernel_launch(void* const* d_in, const int* in_sizes, int n_in,
                              void* d_out, int out_size)
{
    const float* x_feat = (const float*)d_in[0];
    const float* f1_ref = (const float*)d_in[1];
    const float* w1   = (const float*)d_in[2];
    const float* b1   = (const float*)d_in[3];
    const float* wd   = (const float*)d_in[4];
    const float* bd   = (const float*)d_in[5];
    const float* rw00 = (const float*)d_in[6];
    const float* rb00 = (const float*)d_in[7];
    const float* rw01 = (const float*)d_in[8];
    const float* rb01 = (const float*)d_in[9];
    const float* rw10 = (const float*)d_in[10];
    const float* rb10 = (const float*)d_in[11];
    const float* rw11 = (const float*)d_in[12];
    const float* rb11 = (const float*)d_in[13];
    const float* rw12 = (const float*)d_in[14];
    const float* rb12 = (const float*)d_in[15];
    const float* w4   = (const float*)d_in[16];
    const float* b4   = (const float*)d_in[17];
    const int* idx1 = (const int*)d_in[18];
    const int* idxd = (const int*)d_in[19];
    const int* idx2 = (const int*)d_in[20];

    int N  = in_sizes[0] / 64;
    int N2 = in_sizes[19] / 8;

    float *F1, *D0, *D1, *AT8;
    float *WF1, *WFd, *WF0, *WF4, *WFp;
    int *iT2;
    cudaGetSymbolAddress((void**)&F1,  g_F1);
    cudaGetSymbolAddress((void**)&D0,  g_D0);
    cudaGetSymbolAddress((void**)&D1,  g_D1);
    cudaGetSymbolAddress((void**)&AT8, g_AT8);
    cudaGetSymbolAddress((void**)&iT2, g_iT2);
    cudaGetSymbolAddress((void**)&WF1, g_WF1);
    cudaGetSymbolAddress((void**)&WFd, g_WFd);
    cudaGetSymbolAddress((void**)&WF0, g_WF0);
    cudaGetSymbolAddress((void**)&WF4, g_WF4);
    cudaGetSymbolAddress((void**)&WFp, g_WFp);

    long long n4 = (long long)N * 16;

    // ---- conv1 ----
    zero_cnt_kernel<<<1, 32>>>();
    prep_wfrag<<<(27 * 4096 + 255) / 256, 256>>>(w1, WF1, 27, 64, 64);
    build_pairs_fused<27, 13><<<(N + 255) / 256, 256, 256 * 27 * 4>>>(idx1, N);
    {
        constexpr int SMEM = (128 * 64 + 4096) * 4;
        cudaFuncSetAttribute(center_fused,
                             cudaFuncAttributeMaxDynamicSharedMemorySize, SMEM);
        center_fused<<<(N + 127) / 128, 256, SMEM>>>(
            x_feat, f1_ref, WF1 + (size_t)13 * 4096, b1, F1, N);
    }
    {
        constexpr int SMEM = (128 * 64 + 4096) * 4;
        auto kfn = compact_gemm_t<64, true>;
        cudaFuncSetAttribute(kfn, cudaFuncAttributeMaxDynamicSharedMemorySize, SMEM);
        dim3 grid((N + 1023) / 1024, 27);
        kfn<<<grid, 128, SMEM>>>(x_feat, f1_ref, WF1, N, F1);
    }
    relu_cvt_kernel<<<(int)((n4 + 255) / 256), 256>>>(F1, n4);

    // ---- down (compacted: exactly N valid pairs across 8 offsets) ----
    zero_cnt_kernel<<<1, 32>>>();
    prep_wfrag<<<(8 * 2048 + 255) / 256, 256>>>(wd, WFd, 8, 64, 32);
    build_pairs_fused<8, -1><<<(N2 + 255) / 256, 256, 256 * 8 * 4>>>(idxd, N2);
    cudaMemsetAsync(D0, 0, (size_t)N2 * 32 * sizeof(float));
    {
        constexpr int SMEM = (128 * 64 + 2048) * 4;
        auto kfn = compact_gemm_t<32, false>;
        cudaFuncSetAttribute(kfn, cudaFuncAttributeMaxDynamicSharedMemorySize, SMEM);
        dim3 grid((N2 + 1023) / 1024, 8);
        kfn<<<grid, 128, SMEM>>>(F1, nullptr, WFd, N2, D0);
    }
    bias_relu32<<<(int)(((long long)N2 * 8 + 255) / 256), 256>>>(
        D0, bd, (long long)N2 * 8);

    // ---- coarse-lattice prep ----
    transpose256<<<(N2 + 255) / 256, 256, 27 * 256 * 4>>>(idx2, iT2, N2, 27);
    prep_wfrag<<<(81 * 256 + 255) / 256, 256>>>(rw00, WF0, 81, 32, 8);
    prep_wfrag<<<(27 * 256 + 255) / 256, 256>>>(w4,   WF4, 27, 32, 8);
    prep_wfrag<<<(3 * 256 + 255) / 256, 256>>>(rw10,  WFp, 3,  32, 8);

    float* bufs[2] = { D0, D1 };
    for (int i = 0; i < 3; i++) {
        float* in = bufs[i & 1];
        float* ob = bufs[(i + 1) & 1];

        // K1: AT8[:, :8] = relu(conv27(in, rw00)); AT8[:, 8:] = relu(in @ rw10)
        launch_tf32<27, 32, 8, 16, 3, 256, true, false, true, 13>(
            in, iT2, WF0 + (size_t)i * 27 * 256, rb00 + i * 8, AT8,
            WFp + (size_t)i * 256, rb10 + i * 8, AT8 + 8, N2);

        // K2: full inception tail (rw01 conv + rw11 conv + rw12 pw + resid)
        spconv_tail<27><<<(N2 + 255) / 256, 256>>>(
            AT8, iT2,
            rw01 + (size_t)i * 27 * 8 * 16, rb01 + i * 16,
            rw11 + (size_t)i * 27 * 8 * 8,  rb11 + i * 8,
            rw12 + (size_t)i * 8 * 16,      rb12 + i * 16,
            in, ob, N2);
    }

    // enc4: K=27, 32->8, no relu, straight to output
    launch_tf32<27, 32, 8, 8, 3, 256, false, false, false, 0>(
        bufs[1], iT2, WF4, b4, (float*)d_out, nullptr, nullptr, nullptr, N2);
}